// round 1
// baseline (speedup 1.0000x reference)
#include <cuda_runtime.h>
#include <cuda_bf16.h>
#include <math.h>

#define NN 4096
#define EPSV 1e-9f

// ---------------- device scratch (static, allocation-free) ----------------
__device__ float g_prev[NN * 256];        // layer_previous
__device__ float g_Wh[NN * 256];          // Wh of current layer
__device__ float g_part[2 * NN * 256];    // j-split partial propagate sums
__device__ float g_diag[NN];              // diag(adj)
__device__ float g_r[NN];                 // ||Wh_i||

// ---------------- helpers ----------------
__device__ __forceinline__ void fma16(float (&p)[4][4], float4 a, float4 b) {
    p[0][0] += a.x * b.x; p[0][1] += a.x * b.y; p[0][2] += a.x * b.z; p[0][3] += a.x * b.w;
    p[1][0] += a.y * b.x; p[1][1] += a.y * b.y; p[1][2] += a.y * b.z; p[1][3] += a.y * b.w;
    p[2][0] += a.z * b.x; p[2][1] += a.z * b.y; p[2][2] += a.z * b.z; p[2][3] += a.z * b.w;
    p[3][0] += a.w * b.x; p[3][1] += a.w * b.y; p[3][2] += a.w * b.z; p[3][3] += a.w * b.w;
}

__device__ __forceinline__ float softplusf(float z) {
    return (z > 20.f) ? z : log1pf(__expf(z));
}

__device__ __forceinline__ float eluf(float x) {
    return x > 0.f ? x : expm1f(x);
}

// ---------------- diag extraction ----------------
__global__ void diag_kernel(const float* __restrict__ adj, float* __restrict__ dg) {
    int i = blockIdx.x * 256 + threadIdx.x;
    dg[i] = adj[(size_t)i * (NN + 1)];
}

// ---------------- dense GEMM: C[4096,256] = A[4096,K] @ W[K,256] + b ----------------
__global__ __launch_bounds__(256)
void gemm_bias_kernel(const float* __restrict__ A, const float* __restrict__ W,
                      const float* __restrict__ bias, float* __restrict__ C,
                      int K, int do_elu) {
    __shared__ float sA[16][68];
    __shared__ float sB[16][68];
    const int tid = threadIdx.x;
    const int ty = tid >> 4, tx = tid & 15;
    const int i0 = blockIdx.x * 64, j0 = blockIdx.y * 64;
    const int mload = tid >> 4;    // 0..15
    const int kload = tid & 15;    // 0..15
    const int kload2 = tid >> 6;   // 0..3
    const int nload = tid & 63;    // 0..63

    float p[4][4];
#pragma unroll
    for (int u = 0; u < 4; u++)
#pragma unroll
        for (int v = 0; v < 4; v++) p[u][v] = 0.f;

    for (int kb = 0; kb < K; kb += 16) {
        __syncthreads();
#pragma unroll
        for (int r = 0; r < 4; r++)
            sA[kload][mload + 16 * r] = A[(size_t)(i0 + mload + 16 * r) * K + kb + kload];
#pragma unroll
        for (int r = 0; r < 4; r++)
            sB[kload2 + 4 * r][nload] = W[(size_t)(kb + kload2 + 4 * r) * 256 + j0 + nload];
        __syncthreads();
#pragma unroll
        for (int kk = 0; kk < 16; kk++) {
            float4 a = *(const float4*)&sA[kk][4 * ty];
            float4 b = *(const float4*)&sB[kk][4 * tx];
            fma16(p, a, b);
        }
    }
#pragma unroll
    for (int u = 0; u < 4; u++) {
#pragma unroll
        for (int v = 0; v < 4; v++) {
            float val = p[u][v] + __ldg(bias + j0 + 4 * tx + v);
            if (do_elu) val = eluf(val);
            C[(size_t)(i0 + 4 * ty + u) * 256 + j0 + 4 * tx + v] = val;
        }
    }
}

// ---------------- small GEMM for layer 3: Wh16 = prev @ W3 + b3 ----------------
__global__ void wh16_kernel(const float* __restrict__ H, const float* __restrict__ W3,
                            const float* __restrict__ b3, float* __restrict__ Wh) {
    int idx = blockIdx.x * blockDim.x + threadIdx.x;  // 65536
    int i = idx >> 4, c = idx & 15;
    const float* h = H + (size_t)i * 256;
    float s = __ldg(b3 + c);
#pragma unroll 8
    for (int k = 0; k < 256; k++) s += h[k] * __ldg(W3 + k * 16 + c);
    Wh[idx] = s;
}

// ---------------- row norms: r_i = ||Wh_i|| ----------------
__global__ void rownorm_kernel(const float* __restrict__ Wh, float* __restrict__ r, int D) {
    int row = blockIdx.x * 8 + (threadIdx.x >> 5);
    int lane = threadIdx.x & 31;
    float s = 0.f;
    for (int k = lane; k < D; k += 32) {
        float v = Wh[(size_t)row * D + k];
        s += v * v;
    }
#pragma unroll
    for (int o = 16; o; o >>= 1) s += __shfl_xor_sync(0xffffffffu, s, o);
    if (lane == 0) r[row] = sqrtf(s);
}

// ---------------- fused attention layer ----------------
// Computes part[split] = sum_j (signsel(c0,c1) * att[i,j]) * Wh[j,:]
// where att = (cos_sim * adj * softplus(dc0*degp+dc1)), diag zeroed.
template <int D>
__global__ __launch_bounds__(256, 1)
void fused_layer(const float* __restrict__ Wh, const float* __restrict__ rvec,
                 const float* __restrict__ diagv, const float* __restrict__ adj,
                 const float* __restrict__ dc, const float* __restrict__ cf,
                 float* __restrict__ part) {
    constexpr int PT = 68;        // pitch for transposed tiles
    constexpr int PJ = D + 8;     // pitch for row-major Wh_j tile
    constexpr int NACC = D / 16;  // 16 (D=256) or 1 (D=16)
    extern __shared__ float sm[];
    float* sIT = sm;                 // [D][PT]   Wh_i transposed
    float* sJT = sIT + D * PT;       // [D][PT]   Wh_j transposed (score)
    float* sJ = sJT + D * PT;        // [64][PJ]  Wh_j row-major (propagate)
    float* sWT = sJ + 64 * PJ;       // [64][PT]  weight tile transposed [j][i]
    __shared__ float sRi[64], sRj[64], sDi[64];

    const int tid = threadIdx.x;
    const int ty = tid >> 4, tx = tid & 15;
    const int i0 = blockIdx.x * 64;
    const int jbase = blockIdx.y * (NN / 2);

    // per-layer scalar params
    float dc0 = __ldg(dc), dc1 = __ldg(dc + 1);
    float f0 = __ldg(cf), f1 = __ldg(cf + 1), f2 = __ldg(cf + 2);
    float mxc = fmaxf(f0, fmaxf(f1, f2));
    float e0 = __expf(f0 - mxc), e1 = __expf(f1 - mxc), e2 = __expf(f2 - mxc);
    float inv = 1.f / (e0 + e1 + e2);
    float c0 = e0 * inv, c1 = e1 * inv;

    // load Wh_i tile (transposed) once per CTA
    for (int idx = tid; idx < 64 * D; idx += 256) {
        int m = idx / D, k = idx % D;
        sIT[k * PT + m] = Wh[(size_t)(i0 + m) * D + k];
    }
    if (tid < 64) {
        sRi[tid] = rvec[i0 + tid];
        sDi[tid] = diagv[i0 + tid];
    }

    float acc[4][NACC];
#pragma unroll
    for (int u = 0; u < 4; u++)
#pragma unroll
        for (int q = 0; q < NACC; q++) acc[u][q] = 0.f;

    for (int jt = 0; jt < (NN / 2) / 64; jt++) {
        int j0 = jbase + jt * 64;
        __syncthreads();
        for (int idx = tid; idx < 64 * D; idx += 256) {
            int n = idx / D, k = idx % D;
            float v = Wh[(size_t)(j0 + n) * D + k];
            sJT[k * PT + n] = v;
            sJ[n * PJ + k] = v;
        }
        if (tid < 64) sRj[tid] = rvec[j0 + tid];
        __syncthreads();

        // ---- score GEMM: p = Wh_i @ Wh_j^T (64x64 tile, 4x4 per thread) ----
        float p[4][4];
#pragma unroll
        for (int u = 0; u < 4; u++)
#pragma unroll
            for (int v = 0; v < 4; v++) p[u][v] = 0.f;

#pragma unroll 4
        for (int k = 0; k < D; k++) {
            float4 a = *(const float4*)(sIT + k * PT + 4 * ty);
            float4 b = *(const float4*)(sJT + k * PT + 4 * tx);
            fma16(p, a, b);
        }

        // ---- weight computation ----
#pragma unroll
        for (int u = 0; u < 4; u++) {
            int li = 4 * ty + u;
            int gi = i0 + li;
            float ri = sRi[li], di = sDi[li];
            const float* arow = adj + (size_t)gi * NN + j0;
#pragma unroll
            for (int v = 0; v < 4; v++) {
                int lj = 4 * tx + v;
                int gj = j0 + lj;
                float aij = __ldg(arow + lj);
                float am = fmaxf(aij, EPSV);
                float z = dc0 * (di / am - 1.f) + dc1;
                float sc = softplusf(z);
                float den = fmaxf(ri * sRj[lj], EPSV);
                float e = p[u][v] / den;
                if (gi == gj) e = 0.f;
                float att = e * aij * sc;
                float w = (att > 0.f ? c0 : c1) * att;
                sWT[lj * PT + li] = w;
            }
        }
        __syncthreads();

        // ---- propagate GEMM: acc += W_tile @ Wh_j ----
        if constexpr (D == 256) {
#pragma unroll 2
            for (int j = 0; j < 64; j++) {
                float4 w4 = *(const float4*)(sWT + j * PT + 4 * ty);
                const float* bj = sJ + j * PJ + 4 * tx;
#pragma unroll
                for (int q = 0; q < 4; q++) {
                    float4 b = *(const float4*)(bj + 64 * q);
                    acc[0][4 * q + 0] += w4.x * b.x; acc[0][4 * q + 1] += w4.x * b.y;
                    acc[0][4 * q + 2] += w4.x * b.z; acc[0][4 * q + 3] += w4.x * b.w;
                    acc[1][4 * q + 0] += w4.y * b.x; acc[1][4 * q + 1] += w4.y * b.y;
                    acc[1][4 * q + 2] += w4.y * b.z; acc[1][4 * q + 3] += w4.y * b.w;
                    acc[2][4 * q + 0] += w4.z * b.x; acc[2][4 * q + 1] += w4.z * b.y;
                    acc[2][4 * q + 2] += w4.z * b.z; acc[2][4 * q + 3] += w4.z * b.w;
                    acc[3][4 * q + 0] += w4.w * b.x; acc[3][4 * q + 1] += w4.w * b.y;
                    acc[3][4 * q + 2] += w4.w * b.z; acc[3][4 * q + 3] += w4.w * b.w;
                }
            }
        } else {
#pragma unroll 4
            for (int j = 0; j < 64; j++) {
                float4 w4 = *(const float4*)(sWT + j * PT + 4 * ty);
                float b = sJ[j * PJ + tx];
                acc[0][0] += w4.x * b;
                acc[1][0] += w4.y * b;
                acc[2][0] += w4.z * b;
                acc[3][0] += w4.w * b;
            }
        }
    }

    float* out = part + (size_t)blockIdx.y * NN * D;
#pragma unroll
    for (int u = 0; u < 4; u++) {
        int gi = i0 + 4 * ty + u;
        if constexpr (D == 256) {
#pragma unroll
            for (int q = 0; q < 4; q++) {
                float4 v4 = make_float4(acc[u][4 * q], acc[u][4 * q + 1],
                                        acc[u][4 * q + 2], acc[u][4 * q + 3]);
                *(float4*)(out + (size_t)gi * D + 64 * q + 4 * tx) = v4;
            }
        } else {
            out[(size_t)gi * D + tx] = acc[u][0];
        }
    }
}

// ---------------- epilogue for layers 0..2: prev += coeff*elu(s*(P + c2*Wh)) ----------------
__global__ void epi_kernel(const float* __restrict__ part, const float* __restrict__ Wh,
                           float* __restrict__ prev,
                           const float* __restrict__ cf, const float* __restrict__ sp,
                           float coeff) {
    int idx = blockIdx.x * 256 + threadIdx.x;
    float f0 = __ldg(cf), f1 = __ldg(cf + 1), f2 = __ldg(cf + 2);
    float mxc = fmaxf(f0, fmaxf(f1, f2));
    float e0 = __expf(f0 - mxc), e1 = __expf(f1 - mxc), e2 = __expf(f2 - mxc);
    float c2 = e2 / (e0 + e1 + e2);
    float s = softplusf(__ldg(sp));
    float inner = s * (part[idx] + part[(size_t)NN * 256 + idx] + c2 * Wh[idx]);
    prev[idx] += coeff * eluf(inner);
}

// ---------------- final: log_softmax over 16 classes ----------------
__global__ void final_kernel(const float* __restrict__ part, const float* __restrict__ Wh,
                             const float* __restrict__ cf, const float* __restrict__ sp,
                             float* __restrict__ out) {
    int row = blockIdx.x * blockDim.x + threadIdx.x;  // 4096 rows
    float f0 = __ldg(cf), f1 = __ldg(cf + 1), f2 = __ldg(cf + 2);
    float mxc = fmaxf(f0, fmaxf(f1, f2));
    float e0 = __expf(f0 - mxc), e1 = __expf(f1 - mxc), e2 = __expf(f2 - mxc);
    float c2 = e2 / (e0 + e1 + e2);
    float s = softplusf(__ldg(sp));

    float v[16];
    float mx = -3.4e38f;
#pragma unroll
    for (int c = 0; c < 16; c++) {
        float t = s * (part[row * 16 + c] + part[(size_t)NN * 16 + row * 16 + c] +
                       c2 * Wh[row * 16 + c]);
        v[c] = t;
        mx = fmaxf(mx, t);
    }
    float lse = 0.f;
#pragma unroll
    for (int c = 0; c < 16; c++) lse += expf(v[c] - mx);
    lse = logf(lse);
#pragma unroll
    for (int c = 0; c < 16; c++) out[row * 16 + c] = v[c] - mx - lse;
}

// ---------------- host launcher ----------------
extern "C" void kernel_launch(void* const* d_in, const int* in_sizes, int n_in,
                              void* d_out, int out_size) {
    const float* x   = (const float*)d_in[0];
    const float* adj = (const float*)d_in[1];
    const float* Wf  = (const float*)d_in[2];
    const float* bf  = (const float*)d_in[3];
    const float* W0  = (const float*)d_in[4];
    const float* b0  = (const float*)d_in[5];
    const float* W1  = (const float*)d_in[6];
    const float* b1  = (const float*)d_in[7];
    const float* W2  = (const float*)d_in[8];
    const float* b2  = (const float*)d_in[9];
    const float* W3  = (const float*)d_in[10];
    const float* b3  = (const float*)d_in[11];
    const float* dcs = (const float*)d_in[12];  // [4,2]
    const float* cfs = (const float*)d_in[13];  // [4,3]
    const float* sps = (const float*)d_in[14];  // [4,1]
    float* out = (float*)d_out;

    float *p_prev, *p_Wh, *p_part, *p_diag, *p_r;
    cudaGetSymbolAddress((void**)&p_prev, g_prev);
    cudaGetSymbolAddress((void**)&p_Wh, g_Wh);
    cudaGetSymbolAddress((void**)&p_part, g_part);
    cudaGetSymbolAddress((void**)&p_diag, g_diag);
    cudaGetSymbolAddress((void**)&p_r, g_r);

    const int SMEM256 = (256 * 68 * 2 + 64 * 264 + 64 * 68) * 4;  // 224256 B
    const int SMEM16  = (16 * 68 * 2 + 64 * 24 + 64 * 68) * 4;    // 32256 B
    cudaFuncSetAttribute(fused_layer<256>, cudaFuncAttributeMaxDynamicSharedMemorySize, SMEM256);

    const float cI1 = 1.0f;
    const float cI2 = logf(1.0f / 27.0f + 1.0f);
    const float cI3 = logf(1.0f / 64.0f + 1.0f);

    diag_kernel<<<NN / 256, 256>>>(adj, p_diag);
    // feed: prev = elu(x @ Wf + bf)
    gemm_bias_kernel<<<dim3(64, 4), 256>>>(x, Wf, bf, p_prev, 512, 1);

    // ---- layer 0 (input x, K=512) ----
    gemm_bias_kernel<<<dim3(64, 4), 256>>>(x, W0, b0, p_Wh, 512, 0);
    rownorm_kernel<<<512, 256>>>(p_Wh, p_r, 256);
    fused_layer<256><<<dim3(64, 2), 256, SMEM256>>>(p_Wh, p_r, p_diag, adj, dcs + 0, cfs + 0, p_part);
    epi_kernel<<<NN, 256>>>(p_part, p_Wh, p_prev, cfs + 0, sps + 0, cI1);

    // ---- layer 1 ----
    gemm_bias_kernel<<<dim3(64, 4), 256>>>(p_prev, W1, b1, p_Wh, 256, 0);
    rownorm_kernel<<<512, 256>>>(p_Wh, p_r, 256);
    fused_layer<256><<<dim3(64, 2), 256, SMEM256>>>(p_Wh, p_r, p_diag, adj, dcs + 2, cfs + 3, p_part);
    epi_kernel<<<NN, 256>>>(p_part, p_Wh, p_prev, cfs + 3, sps + 1, cI2);

    // ---- layer 2 ----
    gemm_bias_kernel<<<dim3(64, 4), 256>>>(p_prev, W2, b2, p_Wh, 256, 0);
    rownorm_kernel<<<512, 256>>>(p_Wh, p_r, 256);
    fused_layer<256><<<dim3(64, 2), 256, SMEM256>>>(p_Wh, p_r, p_diag, adj, dcs + 4, cfs + 6, p_part);
    epi_kernel<<<NN, 256>>>(p_part, p_Wh, p_prev, cfs + 6, sps + 2, cI3);

    // ---- layer 3 (D=16) ----
    wh16_kernel<<<256, 256>>>(p_prev, W3, b3, p_Wh);
    rownorm_kernel<<<512, 256>>>(p_Wh, p_r, 16);
    fused_layer<16><<<dim3(64, 2), 256, SMEM16>>>(p_Wh, p_r, p_diag, adj, dcs + 6, cfs + 9, p_part);
    final_kernel<<<NN / 256, 256>>>(p_part, p_Wh, cfs + 9, sps + 3, out);
}

// round 4
// speedup vs baseline: 2.4566x; 2.4566x over previous
#include <cuda_runtime.h>
#include <cuda_bf16.h>
#include <math.h>
#include <stdint.h>

#define NN 4096
#define EPSV 1e-9f

// ---------------- device scratch (static, allocation-free) ----------------
__device__ float g_prev[NN * 256];
__device__ float g_Wh[NN * 256];
__device__ float g_part[4 * NN * 256];   // 4-way j-split partial propagate sums
__device__ float g_diag[NN];
__device__ float g_r[NN];

// ---------------- helpers ----------------
__device__ __forceinline__ uint32_t smem_u32(const void* p) {
    return (uint32_t)__cvta_generic_to_shared((void*)p);
}

__device__ __forceinline__ void ldsm4(uint32_t* r, uint32_t addr) {
    asm volatile("ldmatrix.sync.aligned.m8n8.x4.shared.b16 {%0,%1,%2,%3}, [%4];"
                 : "=r"(r[0]), "=r"(r[1]), "=r"(r[2]), "=r"(r[3]) : "r"(addr));
}
__device__ __forceinline__ void ldsm4t(uint32_t* r, uint32_t addr) {
    asm volatile("ldmatrix.sync.aligned.m8n8.x4.trans.shared.b16 {%0,%1,%2,%3}, [%4];"
                 : "=r"(r[0]), "=r"(r[1]), "=r"(r[2]), "=r"(r[3]) : "r"(addr));
}
__device__ __forceinline__ void mma_bf16(float* c, const uint32_t* a, uint32_t b0, uint32_t b1) {
    asm volatile("mma.sync.aligned.m16n8k16.row.col.f32.bf16.bf16.f32 "
                 "{%0,%1,%2,%3}, {%4,%5,%6,%7}, {%8,%9}, {%0,%1,%2,%3};"
                 : "+f"(c[0]), "+f"(c[1]), "+f"(c[2]), "+f"(c[3])
                 : "r"(a[0]), "r"(a[1]), "r"(a[2]), "r"(a[3]), "r"(b0), "r"(b1));
}

__device__ __forceinline__ float softplusf(float z) {
    return (z > 15.f) ? z : __logf(1.f + __expf(z));
}
__device__ __forceinline__ float eluf(float x) { return x > 0.f ? x : expm1f(x); }

__device__ __forceinline__ void fma16(float (&p)[4][4], float4 a, float4 b) {
    p[0][0] += a.x * b.x; p[0][1] += a.x * b.y; p[0][2] += a.x * b.z; p[0][3] += a.x * b.w;
    p[1][0] += a.y * b.x; p[1][1] += a.y * b.y; p[1][2] += a.y * b.z; p[1][3] += a.y * b.w;
    p[2][0] += a.z * b.x; p[2][1] += a.z * b.y; p[2][2] += a.z * b.z; p[2][3] += a.z * b.w;
    p[3][0] += a.w * b.x; p[3][1] += a.w * b.y; p[3][2] += a.w * b.z; p[3][3] += a.w * b.w;
}

// pack two floats into bf16x2 hi and lo (split precision)
__device__ __forceinline__ void pack_hl(float w0, float w1, uint32_t& hi, uint32_t& lo) {
    __nv_bfloat162 h = __floats2bfloat162_rn(w0, w1);
    float2 hf = __bfloat1622float2(h);
    __nv_bfloat162 l = __floats2bfloat162_rn(w0 - hf.x, w1 - hf.y);
    hi = *(uint32_t*)&h;
    lo = *(uint32_t*)&l;
}

// fp32 src rows -> swizzled bf16 hi/lo SMEM tiles.
// (row,k) chunk layout: byte = row*(2*D) + (((k>>3) ^ (row&7)) * 16) + (k&7)*2
template <int ROWS, int D>
__device__ __forceinline__ void cvt_fill(const float* __restrict__ src,
                                         char* __restrict__ hi, char* __restrict__ lo, int tid) {
    constexpr int CH = D / 8;           // 16B chunks per row
    constexpr int NIT = ROWS * CH;
#pragma unroll 4
    for (int it = tid; it < NIT; it += 256) {
        int row = it / CH;
        int c = it % CH;
        int k = c * 8;
        const float* s = src + (size_t)row * D + k;
        float4 v0 = __ldg((const float4*)s);
        float4 v1 = __ldg((const float4*)(s + 4));
        uint32_t off = (uint32_t)row * (2 * D) + (uint32_t)((c ^ (row & 7)) * 16);
        __nv_bfloat162 h0 = __floats2bfloat162_rn(v0.x, v0.y);
        __nv_bfloat162 h1 = __floats2bfloat162_rn(v0.z, v0.w);
        __nv_bfloat162 h2 = __floats2bfloat162_rn(v1.x, v1.y);
        __nv_bfloat162 h3 = __floats2bfloat162_rn(v1.z, v1.w);
        float2 f0 = __bfloat1622float2(h0), f1 = __bfloat1622float2(h1);
        float2 f2 = __bfloat1622float2(h2), f3 = __bfloat1622float2(h3);
        __nv_bfloat162 l0 = __floats2bfloat162_rn(v0.x - f0.x, v0.y - f0.y);
        __nv_bfloat162 l1 = __floats2bfloat162_rn(v0.z - f1.x, v0.w - f1.y);
        __nv_bfloat162 l2 = __floats2bfloat162_rn(v1.x - f2.x, v1.y - f2.y);
        __nv_bfloat162 l3 = __floats2bfloat162_rn(v1.z - f3.x, v1.w - f3.y);
        *(uint4*)(hi + off) = make_uint4(*(uint32_t*)&h0, *(uint32_t*)&h1,
                                         *(uint32_t*)&h2, *(uint32_t*)&h3);
        *(uint4*)(lo + off) = make_uint4(*(uint32_t*)&l0, *(uint32_t*)&l1,
                                         *(uint32_t*)&l2, *(uint32_t*)&l3);
    }
}

// ---------------- small kernels ----------------
__global__ void diag_kernel(const float* __restrict__ adj, float* __restrict__ dg) {
    int i = blockIdx.x * 256 + threadIdx.x;
    dg[i] = adj[(size_t)i * (NN + 1)];
}

__global__ __launch_bounds__(256)
void gemm_bias_kernel(const float* __restrict__ A, const float* __restrict__ W,
                      const float* __restrict__ bias, float* __restrict__ C,
                      int K, int do_elu) {
    __shared__ float sA[16][68];
    __shared__ float sB[16][68];
    const int tid = threadIdx.x;
    const int ty = tid >> 4, tx = tid & 15;
    const int i0 = blockIdx.x * 64, j0 = blockIdx.y * 64;
    const int mload = tid >> 4;
    const int kload = tid & 15;
    const int kload2 = tid >> 6;
    const int nload = tid & 63;

    float p[4][4];
#pragma unroll
    for (int u = 0; u < 4; u++)
#pragma unroll
        for (int v = 0; v < 4; v++) p[u][v] = 0.f;

    for (int kb = 0; kb < K; kb += 16) {
        __syncthreads();
#pragma unroll
        for (int r = 0; r < 4; r++)
            sA[kload][mload + 16 * r] = A[(size_t)(i0 + mload + 16 * r) * K + kb + kload];
#pragma unroll
        for (int r = 0; r < 4; r++)
            sB[kload2 + 4 * r][nload] = W[(size_t)(kb + kload2 + 4 * r) * 256 + j0 + nload];
        __syncthreads();
#pragma unroll
        for (int kk = 0; kk < 16; kk++) {
            float4 a = *(const float4*)&sA[kk][4 * ty];
            float4 b = *(const float4*)&sB[kk][4 * tx];
            fma16(p, a, b);
        }
    }
#pragma unroll
    for (int u = 0; u < 4; u++) {
#pragma unroll
        for (int v = 0; v < 4; v++) {
            float val = p[u][v] + __ldg(bias + j0 + 4 * tx + v);
            if (do_elu) val = eluf(val);
            C[(size_t)(i0 + 4 * ty + u) * 256 + j0 + 4 * tx + v] = val;
        }
    }
}

// layer 3: Wh64 = zero-pad(prev @ W3 + b3) to [N,64]
__global__ void wh16_kernel(const float* __restrict__ H, const float* __restrict__ W3,
                            const float* __restrict__ b3, float* __restrict__ Wh) {
    int idx = blockIdx.x * 256 + threadIdx.x;  // NN*64
    int i = idx >> 6, c = idx & 63;
    float s = 0.f;
    if (c < 16) {
        s = __ldg(b3 + c);
        const float* h = H + (size_t)i * 256;
#pragma unroll 8
        for (int k = 0; k < 256; k++) s += h[k] * __ldg(W3 + k * 16 + c);
    }
    Wh[idx] = s;
}

__global__ void rownorm_kernel(const float* __restrict__ Wh, float* __restrict__ r, int D) {
    int row = blockIdx.x * 8 + (threadIdx.x >> 5);
    int lane = threadIdx.x & 31;
    float s = 0.f;
    for (int k = lane; k < D; k += 32) {
        float v = Wh[(size_t)row * D + k];
        s += v * v;
    }
#pragma unroll
    for (int o = 16; o; o >>= 1) s += __shfl_xor_sync(0xffffffffu, s, o);
    if (lane == 0) r[row] = sqrtf(s);
}

// ---------------- fused mma.sync attention layer ----------------
// grid (32, 4): 128-row i tiles x 4-way j split; 256 threads, 8 warps over i.
template <int D>  // 256, or 64 (layer 3 zero-padded)
__global__ __launch_bounds__(256, 1)
void fused_mma(const float* __restrict__ Wh, const float* __restrict__ rvec,
               const float* __restrict__ diagv, const float* __restrict__ adj,
               const float* __restrict__ dc, const float* __restrict__ cf,
               float* __restrict__ part) {
    constexpr int KCH = D / 16;   // score k-chunks
    constexpr int DNB = D / 8;    // propagate n-blocks (P accumulators)
    constexpr int ROWB = 2 * D;   // smem row bytes

    extern __shared__ char sm[];
    char* Ah = sm;
    char* Al = sm + 128 * ROWB;
    char* Bh = sm + 2 * 128 * ROWB;
    char* Bl = Bh + 64 * ROWB;
    const uint32_t ah_b = smem_u32(Ah);
    const uint32_t al_b = smem_u32(Al);
    const uint32_t bh_b = smem_u32(Bh);
    const uint32_t bl_b = smem_u32(Bl);

    const int tid = threadIdx.x;
    const int w = tid >> 5, lane = tid & 31;
    const int i0 = blockIdx.x * 128;
    const int jbase = blockIdx.y * (NN / 4);
    const int row0 = lane >> 2;       // 0..7
    const int qp = lane & 3;          // pair index
    const int gi0 = i0 + w * 16 + row0;

    // ldmatrix lane addressing pieces
    const int lrow = lane & 15;       // row within 16-row tile
    const int lsel = lane >> 4;       // 0/1 -> +8 k (or +8 d)
    const int lx7 = lane & 7;

    // per-layer scalars
    float dc0 = __ldg(dc), dc1 = __ldg(dc + 1);
    float f0 = __ldg(cf), f1 = __ldg(cf + 1), f2 = __ldg(cf + 2);
    float mxc = fmaxf(f0, fmaxf(f1, f2));
    float e0 = __expf(f0 - mxc), e1 = __expf(f1 - mxc), e2 = __expf(f2 - mxc);
    float inv = 1.f / (e0 + e1 + e2);
    float c0 = e0 * inv, c1 = e1 * inv;
    float ri0 = __ldg(rvec + gi0), ri8 = __ldg(rvec + gi0 + 8);
    float di0 = __ldg(diagv + gi0), di8 = __ldg(diagv + gi0 + 8);

    // persistent A tile (Whi hi/lo)
    cvt_fill<128, D>(Wh + (size_t)i0 * D, Ah, Al, tid);

    float pacc[DNB][4];
#pragma unroll
    for (int q = 0; q < DNB; q++)
#pragma unroll
        for (int v = 0; v < 4; v++) pacc[q][v] = 0.f;

    const int arow = w * 16 + lrow;   // A ldmatrix row for this lane

    for (int tt = 0; tt < 16; tt++) {
        int j0 = jbase + tt * 64;
        __syncthreads();              // prior propagate done reading B (iter0: A ready)
        cvt_fill<64, D>(Wh + (size_t)j0 * D, Bh, Bl, tid);
        __syncthreads();

        // ---- score: S[16x64] per warp, bf16x3 ----
        float sacc[8][4];
#pragma unroll
        for (int q = 0; q < 8; q++)
#pragma unroll
            for (int v = 0; v < 4; v++) sacc[q][v] = 0.f;

#pragma unroll
        for (int kc = 0; kc < KCH; kc++) {
            uint32_t achunk = (uint32_t)(((kc * 2 + lsel) ^ lx7) * 16);
            uint32_t ah[4], al_[4];
            ldsm4(ah, ah_b + (uint32_t)arow * ROWB + achunk);
            ldsm4(al_, al_b + (uint32_t)arow * ROWB + achunk);
#pragma unroll
            for (int nh = 0; nh < 2; nh++) {
#pragma unroll
                for (int t = 0; t < 2; t++) {
                    int n00 = nh * 32 + t * 16;
                    uint32_t brow = (uint32_t)(n00 + lrow);
                    uint32_t boff = brow * ROWB + (uint32_t)(((kc * 2 + lsel) ^ (brow & 7)) * 16);
                    uint32_t bh[4], bl[4];
                    ldsm4(bh, bh_b + boff);
                    ldsm4(bl, bl_b + boff);
                    int nb = nh * 4 + t * 2;
                    mma_bf16(sacc[nb],     ah,  bh[0], bh[2]);
                    mma_bf16(sacc[nb + 1], ah,  bh[1], bh[3]);
                    mma_bf16(sacc[nb],     ah,  bl[0], bl[2]);
                    mma_bf16(sacc[nb + 1], ah,  bl[1], bl[3]);
                    mma_bf16(sacc[nb],     al_, bh[0], bh[2]);
                    mma_bf16(sacc[nb + 1], al_, bh[1], bh[3]);
                }
            }
        }

        // ---- weight epilogue: S -> w (A-fragments for propagate, in regs) ----
        uint32_t wh[4][4], wl[4][4];
#pragma unroll
        for (int nb = 0; nb < 8; nb++) {
            int jp = j0 + nb * 8 + 2 * qp;
            float2 aj0 = __ldg((const float2*)(adj + (size_t)gi0 * NN + jp));
            float2 aj8 = __ldg((const float2*)(adj + (size_t)(gi0 + 8) * NN + jp));
            float2 rj = __ldg((const float2*)(rvec + jp));

            float ww[4];
            float sv[4] = {sacc[nb][0], sacc[nb][1], sacc[nb][2], sacc[nb][3]};
            float av[4] = {aj0.x, aj0.y, aj8.x, aj8.y};
            float rv[4] = {rj.x, rj.y, rj.x, rj.y};
            float riv[4] = {ri0, ri0, ri8, ri8};
            float div_[4] = {di0, di0, di8, di8};
            int giv[4] = {gi0, gi0, gi0 + 8, gi0 + 8};
            int gjv[4] = {jp, jp + 1, jp, jp + 1};
#pragma unroll
            for (int u = 0; u < 4; u++) {
                float a = av[u];
                float am = fmaxf(a, EPSV);
                float z = dc0 * (div_[u] * __frcp_rn(am) - 1.f) + dc1;
                float sp = softplusf(z);
                float e = sv[u] * __frcp_rn(fmaxf(riv[u] * rv[u], EPSV));
                float att = e * a * sp;
                if (giv[u] == gjv[u]) att = 0.f;
                ww[u] = (att > 0.f ? c0 : c1) * att;
            }
            int kc = nb >> 1, o = (nb & 1) * 2;
            pack_hl(ww[0], ww[1], wh[kc][o], wl[kc][o]);
            pack_hl(ww[2], ww[3], wh[kc][o + 1], wl[kc][o + 1]);
        }

        // ---- propagate: P += w @ Whj (B via ldmatrix.trans), bf16x3 ----
#pragma unroll
        for (int kc = 0; kc < 4; kc++) {
            uint32_t jrow = (uint32_t)(kc * 16 + lrow);
#pragma unroll
            for (int dt = 0; dt < D / 16; dt++) {
                uint32_t boff = jrow * ROWB + (uint32_t)(((dt * 2 + lsel) ^ (jrow & 7)) * 16);
                uint32_t bh[4], bl[4];
                ldsm4t(bh, bh_b + boff);
                ldsm4t(bl, bl_b + boff);
                int p0 = dt * 2, p1 = dt * 2 + 1;
                mma_bf16(pacc[p0], wh[kc], bh[0], bh[1]);
                mma_bf16(pacc[p1], wh[kc], bh[2], bh[3]);
                mma_bf16(pacc[p0], wh[kc], bl[0], bl[1]);
                mma_bf16(pacc[p1], wh[kc], bl[2], bl[3]);
                mma_bf16(pacc[p0], wl[kc], bh[0], bh[1]);
                mma_bf16(pacc[p1], wl[kc], bh[2], bh[3]);
            }
        }
    }

    // ---- writeout ----
    float* dst0 = part + ((size_t)blockIdx.y * NN + gi0) * D;
    float* dst8 = dst0 + 8 * (size_t)D;
#pragma unroll
    for (int q = 0; q < DNB; q++) {
        int d = q * 8 + 2 * qp;
        *(float2*)(dst0 + d) = make_float2(pacc[q][0], pacc[q][1]);
        *(float2*)(dst8 + d) = make_float2(pacc[q][2], pacc[q][3]);
    }
}

// ---------------- epilogue layers 0..2 ----------------
__global__ void epi_kernel(const float* __restrict__ part, const float* __restrict__ Wh,
                           float* __restrict__ prev,
                           const float* __restrict__ cf, const float* __restrict__ sp,
                           float coeff) {
    int idx = blockIdx.x * 256 + threadIdx.x;
    float f0 = __ldg(cf), f1 = __ldg(cf + 1), f2 = __ldg(cf + 2);
    float mxc = fmaxf(f0, fmaxf(f1, f2));
    float e0 = __expf(f0 - mxc), e1 = __expf(f1 - mxc), e2 = __expf(f2 - mxc);
    float c2 = e2 / (e0 + e1 + e2);
    float s = softplusf(__ldg(sp));
    const size_t ST = (size_t)NN * 256;
    float psum = part[idx] + part[ST + idx] + part[2 * ST + idx] + part[3 * ST + idx];
    float inner = s * (psum + c2 * Wh[idx]);
    prev[idx] += coeff * eluf(inner);
}

// ---------------- final: log_softmax over 16 classes (part stride 64) --------
__global__ void final_kernel(const float* __restrict__ part, const float* __restrict__ Wh,
                             const float* __restrict__ cf, const float* __restrict__ sp,
                             float* __restrict__ out) {
    int row = blockIdx.x * blockDim.x + threadIdx.x;
    float f0 = __ldg(cf), f1 = __ldg(cf + 1), f2 = __ldg(cf + 2);
    float mxc = fmaxf(f0, fmaxf(f1, f2));
    float e0 = __expf(f0 - mxc), e1 = __expf(f1 - mxc), e2 = __expf(f2 - mxc);
    float c2 = e2 / (e0 + e1 + e2);
    float s = softplusf(__ldg(sp));
    const size_t ST = (size_t)NN * 64;

    float v[16];
    float mx = -3.4e38f;
#pragma unroll
    for (int c = 0; c < 16; c++) {
        size_t o = (size_t)row * 64 + c;
        float psum = part[o] + part[ST + o] + part[2 * ST + o] + part[3 * ST + o];
        float t = s * (psum + c2 * Wh[(size_t)row * 64 + c]);
        v[c] = t;
        mx = fmaxf(mx, t);
    }
    float lse = 0.f;
#pragma unroll
    for (int c = 0; c < 16; c++) lse += expf(v[c] - mx);
    lse = logf(lse);
#pragma unroll
    for (int c = 0; c < 16; c++) out[row * 16 + c] = v[c] - mx - lse;
}

// ---------------- host launcher ----------------
extern "C" void kernel_launch(void* const* d_in, const int* in_sizes, int n_in,
                              void* d_out, int out_size) {
    const float* x   = (const float*)d_in[0];
    const float* adj = (const float*)d_in[1];
    const float* Wf  = (const float*)d_in[2];
    const float* bf  = (const float*)d_in[3];
    const float* W0  = (const float*)d_in[4];
    const float* b0  = (const float*)d_in[5];
    const float* W1  = (const float*)d_in[6];
    const float* b1  = (const float*)d_in[7];
    const float* W2  = (const float*)d_in[8];
    const float* b2  = (const float*)d_in[9];
    const float* W3  = (const float*)d_in[10];
    const float* b3  = (const float*)d_in[11];
    const float* dcs = (const float*)d_in[12];
    const float* cfs = (const float*)d_in[13];
    const float* sps = (const float*)d_in[14];
    float* out = (float*)d_out;

    float *p_prev, *p_Wh, *p_part, *p_diag, *p_r;
    cudaGetSymbolAddress((void**)&p_prev, g_prev);
    cudaGetSymbolAddress((void**)&p_Wh, g_Wh);
    cudaGetSymbolAddress((void**)&p_part, g_part);
    cudaGetSymbolAddress((void**)&p_diag, g_diag);
    cudaGetSymbolAddress((void**)&p_r, g_r);

    const int SM256 = (2 * 128 + 2 * 64) * 2 * 256;  // 196608 B
    const int SM64  = (2 * 128 + 2 * 64) * 2 * 64;   //  49152 B
    cudaFuncSetAttribute(fused_mma<256>, cudaFuncAttributeMaxDynamicSharedMemorySize, SM256);
    cudaFuncSetAttribute(fused_mma<64>,  cudaFuncAttributeMaxDynamicSharedMemorySize, SM64);

    const float cI1 = 1.0f;
    const float cI2 = logf(1.0f / 27.0f + 1.0f);
    const float cI3 = logf(1.0f / 64.0f + 1.0f);

    diag_kernel<<<NN / 256, 256>>>(adj, p_diag);
    gemm_bias_kernel<<<dim3(64, 4), 256>>>(x, Wf, bf, p_prev, 512, 1);

    // ---- layer 0 ----
    gemm_bias_kernel<<<dim3(64, 4), 256>>>(x, W0, b0, p_Wh, 512, 0);
    rownorm_kernel<<<512, 256>>>(p_Wh, p_r, 256);
    fused_mma<256><<<dim3(32, 4), 256, SM256>>>(p_Wh, p_r, p_diag, adj, dcs + 0, cfs + 0, p_part);
    epi_kernel<<<NN, 256>>>(p_part, p_Wh, p_prev, cfs + 0, sps + 0, cI1);

    // ---- layer 1 ----
    gemm_bias_kernel<<<dim3(64, 4), 256>>>(p_prev, W1, b1, p_Wh, 256, 0);
    rownorm_kernel<<<512, 256>>>(p_Wh, p_r, 256);
    fused_mma<256><<<dim3(32, 4), 256, SM256>>>(p_Wh, p_r, p_diag, adj, dcs + 2, cfs + 3, p_part);
    epi_kernel<<<NN, 256>>>(p_part, p_Wh, p_prev, cfs + 3, sps + 1, cI2);

    // ---- layer 2 ----
    gemm_bias_kernel<<<dim3(64, 4), 256>>>(p_prev, W2, b2, p_Wh, 256, 0);
    rownorm_kernel<<<512, 256>>>(p_Wh, p_r, 256);
    fused_mma<256><<<dim3(32, 4), 256, SM256>>>(p_Wh, p_r, p_diag, adj, dcs + 4, cfs + 6, p_part);
    epi_kernel<<<NN, 256>>>(p_part, p_Wh, p_prev, cfs + 6, sps + 2, cI3);

    // ---- layer 3 (D=16 zero-padded to 64) ----
    wh16_kernel<<<NN * 64 / 256, 256>>>(p_prev, W3, b3, p_Wh);
    rownorm_kernel<<<512, 256>>>(p_Wh, p_r, 64);
    fused_mma<64><<<dim3(32, 4), 256, SM64>>>(p_Wh, p_r, p_diag, adj, dcs + 6, cfs + 9, p_part);
    final_kernel<<<NN / 256, 256>>>(p_part, p_Wh, cfs + 9, sps + 3, out);
}

// round 6
// speedup vs baseline: 2.8496x; 1.1600x over previous
#include <cuda_runtime.h>
#include <cuda_fp16.h>
#include <math.h>
#include <stdint.h>

#define NN 4096
#define EPSV 1e-9f

// ---------------- device scratch (static, allocation-free) ----------------
__device__ float g_prev[NN * 256];
__device__ float g_Wh[NN * 256];
__device__ float g_part[4 * NN * 256];   // 4-way j-split partial propagate sums
__device__ float g_diag[NN];
__device__ float g_r[NN];
__device__ __half g_WhH[NN * 256];       // Wh hi fp16, swizzled chunks
__device__ __half g_WhL[NN * 256];       // Wh lo fp16 (residual), swizzled chunks

// ---------------- asm helpers ----------------
__device__ __forceinline__ uint32_t smem_u32(const void* p) {
    return (uint32_t)__cvta_generic_to_shared((void*)p);
}
__device__ __forceinline__ void ldsm4(uint32_t* r, uint32_t addr) {
    asm volatile("ldmatrix.sync.aligned.m8n8.x4.shared.b16 {%0,%1,%2,%3}, [%4];"
                 : "=r"(r[0]), "=r"(r[1]), "=r"(r[2]), "=r"(r[3]) : "r"(addr));
}
__device__ __forceinline__ void ldsm4t(uint32_t* r, uint32_t addr) {
    asm volatile("ldmatrix.sync.aligned.m8n8.x4.trans.shared.b16 {%0,%1,%2,%3}, [%4];"
                 : "=r"(r[0]), "=r"(r[1]), "=r"(r[2]), "=r"(r[3]) : "r"(addr));
}
__device__ __forceinline__ void mma_f16(float* c, const uint32_t* a, uint32_t b0, uint32_t b1) {
    asm volatile("mma.sync.aligned.m16n8k16.row.col.f32.f16.f16.f32 "
                 "{%0,%1,%2,%3}, {%4,%5,%6,%7}, {%8,%9}, {%0,%1,%2,%3};"
                 : "+f"(c[0]), "+f"(c[1]), "+f"(c[2]), "+f"(c[3])
                 : "r"(a[0]), "r"(a[1]), "r"(a[2]), "r"(a[3]), "r"(b0), "r"(b1));
}
__device__ __forceinline__ void cp16(uint32_t dst, const void* src) {
    asm volatile("cp.async.cg.shared.global [%0], [%1], 16;" :: "r"(dst), "l"(src));
}
#define CP_COMMIT() asm volatile("cp.async.commit_group;" ::: "memory")
#define CP_WAIT0()  asm volatile("cp.async.wait_group 0;" ::: "memory")
#define CP_WAIT1()  asm volatile("cp.async.wait_group 1;" ::: "memory")

// ---------------- math helpers ----------------
__device__ __forceinline__ float softplusf(float z) {
    return (z > 15.f) ? z : __logf(1.f + __expf(z));
}
__device__ __forceinline__ float eluf(float x) { return x > 0.f ? x : expm1f(x); }

__device__ __forceinline__ void fma16(float (&p)[4][4], float4 a, float4 b) {
    p[0][0] += a.x * b.x; p[0][1] += a.x * b.y; p[0][2] += a.x * b.z; p[0][3] += a.x * b.w;
    p[1][0] += a.y * b.x; p[1][1] += a.y * b.y; p[1][2] += a.y * b.z; p[1][3] += a.y * b.w;
    p[2][0] += a.z * b.x; p[2][1] += a.z * b.y; p[2][2] += a.z * b.z; p[2][3] += a.z * b.w;
    p[3][0] += a.w * b.x; p[3][1] += a.w * b.y; p[3][2] += a.w * b.z; p[3][3] += a.w * b.w;
}

// pack two floats into fp16x2 hi and lo (split precision, ~22-bit total)
__device__ __forceinline__ void pack_hl(float w0, float w1, uint32_t& hi, uint32_t& lo) {
    __half2 h = __floats2half2_rn(w0, w1);
    float2 hf = __half22float2(h);
    __half2 l = __floats2half2_rn(w0 - hf.x, w1 - hf.y);
    hi = *(uint32_t*)&h;
    lo = *(uint32_t*)&l;
}

// ---------------- Wh fp32 -> swizzled fp16 hi/lo global arrays --------------
// chunk layout: elem16 offset = row*D + (c ^ (row&7))*8 + (k&7), c = k>>3.
template <int D>
__global__ void cvt_kernel(const float* __restrict__ src,
                           __half* __restrict__ H, __half* __restrict__ L) {
    int idx = blockIdx.x * 256 + threadIdx.x;   // NN*D/8 chunks
    int row = idx / (D / 8);
    int c = idx % (D / 8);
    const float* s = src + (size_t)row * D + c * 8;
    float4 v0 = __ldg((const float4*)s);
    float4 v1 = __ldg((const float4*)(s + 4));
    int dcn = c ^ (row & 7);
    size_t off = (size_t)row * D + dcn * 8;
    __half2 h0 = __floats2half2_rn(v0.x, v0.y), h1 = __floats2half2_rn(v0.z, v0.w);
    __half2 h2 = __floats2half2_rn(v1.x, v1.y), h3 = __floats2half2_rn(v1.z, v1.w);
    float2 f0 = __half22float2(h0), f1 = __half22float2(h1);
    float2 f2 = __half22float2(h2), f3 = __half22float2(h3);
    __half2 l0 = __floats2half2_rn(v0.x - f0.x, v0.y - f0.y);
    __half2 l1 = __floats2half2_rn(v0.z - f1.x, v0.w - f1.y);
    __half2 l2 = __floats2half2_rn(v1.x - f2.x, v1.y - f2.y);
    __half2 l3 = __floats2half2_rn(v1.z - f3.x, v1.w - f3.y);
    *(uint4*)(H + off) = make_uint4(*(uint32_t*)&h0, *(uint32_t*)&h1,
                                    *(uint32_t*)&h2, *(uint32_t*)&h3);
    *(uint4*)(L + off) = make_uint4(*(uint32_t*)&l0, *(uint32_t*)&l1,
                                    *(uint32_t*)&l2, *(uint32_t*)&l3);
}

// ---------------- small kernels ----------------
__global__ void diag_kernel(const float* __restrict__ adj, float* __restrict__ dg) {
    int i = blockIdx.x * 256 + threadIdx.x;
    dg[i] = adj[(size_t)i * (NN + 1)];
}

__global__ __launch_bounds__(256)
void gemm_bias_kernel(const float* __restrict__ A, const float* __restrict__ W,
                      const float* __restrict__ bias, float* __restrict__ C,
                      int K, int do_elu) {
    __shared__ float sA[16][68];
    __shared__ float sB[16][68];
    const int tid = threadIdx.x;
    const int ty = tid >> 4, tx = tid & 15;
    const int i0 = blockIdx.x * 64, j0 = blockIdx.y * 64;
    const int mload = tid >> 4;
    const int kload = tid & 15;
    const int kload2 = tid >> 6;
    const int nload = tid & 63;

    float p[4][4];
#pragma unroll
    for (int u = 0; u < 4; u++)
#pragma unroll
        for (int v = 0; v < 4; v++) p[u][v] = 0.f;

    for (int kb = 0; kb < K; kb += 16) {
        __syncthreads();
#pragma unroll
        for (int r = 0; r < 4; r++)
            sA[kload][mload + 16 * r] = A[(size_t)(i0 + mload + 16 * r) * K + kb + kload];
#pragma unroll
        for (int r = 0; r < 4; r++)
            sB[kload2 + 4 * r][nload] = W[(size_t)(kb + kload2 + 4 * r) * 256 + j0 + nload];
        __syncthreads();
#pragma unroll
        for (int kk = 0; kk < 16; kk++) {
            float4 a = *(const float4*)&sA[kk][4 * ty];
            float4 b = *(const float4*)&sB[kk][4 * tx];
            fma16(p, a, b);
        }
    }
#pragma unroll
    for (int u = 0; u < 4; u++) {
#pragma unroll
        for (int v = 0; v < 4; v++) {
            float val = p[u][v] + __ldg(bias + j0 + 4 * tx + v);
            if (do_elu) val = eluf(val);
            C[(size_t)(i0 + 4 * ty + u) * 256 + j0 + 4 * tx + v] = val;
        }
    }
}

// layer 3: Wh64 = zero-pad(prev @ W3 + b3) to [N,64]
__global__ void wh16_kernel(const float* __restrict__ H, const float* __restrict__ W3,
                            const float* __restrict__ b3, float* __restrict__ Wh) {
    int idx = blockIdx.x * 256 + threadIdx.x;  // NN*64
    int i = idx >> 6, c = idx & 63;
    float s = 0.f;
    if (c < 16) {
        s = __ldg(b3 + c);
        const float* h = H + (size_t)i * 256;
#pragma unroll 8
        for (int k = 0; k < 256; k++) s += h[k] * __ldg(W3 + k * 16 + c);
    }
    Wh[idx] = s;
}

__global__ void rownorm_kernel(const float* __restrict__ Wh, float* __restrict__ r, int D) {
    int row = blockIdx.x * 8 + (threadIdx.x >> 5);
    int lane = threadIdx.x & 31;
    float s = 0.f;
    for (int k = lane; k < D; k += 32) {
        float v = Wh[(size_t)row * D + k];
        s += v * v;
    }
#pragma unroll
    for (int o = 16; o; o >>= 1) s += __shfl_xor_sync(0xffffffffu, s, o);
    if (lane == 0) r[row] = sqrtf(s);
}

// ---------------- fused mma.sync attention layer (fp16 asymmetric split) ----
// grid (32, 4): 128-row i tiles x 4-way j split; 256 threads, 8 warps over i.
// SMEM: Ah[128xD] + Al[128xD] + Bh double buffer (2 x 64xD), all fp16.
template <int D>  // 256, or 64 (layer 3 zero-padded)
__global__ __launch_bounds__(256, 1)
void fused_mma(const __half* __restrict__ WhH, const __half* __restrict__ WhL,
               const float* __restrict__ rvec,
               const float* __restrict__ diagv, const float* __restrict__ adj,
               const float* __restrict__ dc, const float* __restrict__ cf,
               float* __restrict__ part) {
    constexpr int KCH = D / 16;   // score k-chunks
    constexpr int DNB = D / 8;    // propagate n-blocks (P accumulators)
    constexpr int ROWB = 2 * D;   // smem row bytes (fp16)
    constexpr int BBYTES = 64 * ROWB;

    extern __shared__ char sm[];
    char* Ah = sm;
    char* Al = sm + 128 * ROWB;
    char* Bb = sm + 2 * 128 * ROWB;        // two B buffers
    const uint32_t ah_b = smem_u32(Ah);
    const uint32_t al_b = smem_u32(Al);
    const uint32_t bb_b = smem_u32(Bb);

    const int tid = threadIdx.x;
    const int w = tid >> 5, lane = tid & 31;
    const int i0 = blockIdx.x * 128;
    const int jbase = blockIdx.y * (NN / 4);
    const int row0 = lane >> 2;
    const int qp = lane & 3;
    const int gi0 = i0 + w * 16 + row0;

    const int lrow = lane & 15;
    const int lsel = lane >> 4;
    const int lx7 = lane & 7;

    // per-layer scalars
    float dc0 = __ldg(dc), dc1 = __ldg(dc + 1);
    float f0 = __ldg(cf), f1 = __ldg(cf + 1), f2 = __ldg(cf + 2);
    float mxc = fmaxf(f0, fmaxf(f1, f2));
    float e0 = __expf(f0 - mxc), e1 = __expf(f1 - mxc), e2 = __expf(f2 - mxc);
    float inv = 1.f / (e0 + e1 + e2);
    float c0 = e0 * inv, c1 = e1 * inv;
    float ri0 = __ldg(rvec + gi0), ri8 = __ldg(rvec + gi0 + 8);
    float di0 = __ldg(diagv + gi0), di8 = __ldg(diagv + gi0 + 8);

    // A tiles: raw copy (swizzle preserved: i0 multiple of 128 keeps row mod 8)
    {
        const uint4* gH = (const uint4*)(WhH + (size_t)i0 * D);
        const uint4* gL = (const uint4*)(WhL + (size_t)i0 * D);
        uint4* sH = (uint4*)Ah;
        uint4* sL = (uint4*)Al;
#pragma unroll 4
        for (int it = tid; it < 16 * D; it += 256) {
            sH[it] = __ldg(gH + it);
            sL[it] = __ldg(gL + it);
        }
    }

    // prefetch B tile 0 into buffer 0
    {
        const char* src = (const char*)(WhH + (size_t)jbase * D);
        for (int off = tid * 16; off < BBYTES; off += 4096) cp16(bb_b + off, src + off);
        CP_COMMIT();
    }

    float pacc[DNB][4];
#pragma unroll
    for (int q = 0; q < DNB; q++)
#pragma unroll
        for (int v = 0; v < 4; v++) pacc[q][v] = 0.f;

    const int arow = w * 16 + lrow;

    for (int tt = 0; tt < 16; tt++) {
        int j0 = jbase + tt * 64;
        __syncthreads();   // all warps done reading buf[(tt+1)&1] (iter tt-1)
        if (tt + 1 < 16) {
            const char* src = (const char*)(WhH + (size_t)(j0 + 64) * D);
            uint32_t dst = bb_b + ((tt + 1) & 1) * BBYTES;
            for (int off = tid * 16; off < BBYTES; off += 4096) cp16(dst + off, src + off);
            CP_COMMIT();
            CP_WAIT1();
        } else {
            CP_WAIT0();
        }
        __syncthreads();
        const uint32_t bcur = bb_b + (tt & 1) * BBYTES;

        // ---- score: S[16x64] per warp, fp16 split-A x2 ----
        float sacc[8][4];
#pragma unroll
        for (int q = 0; q < 8; q++)
#pragma unroll
            for (int v = 0; v < 4; v++) sacc[q][v] = 0.f;

#pragma unroll
        for (int kc = 0; kc < KCH; kc++) {
            uint32_t achunk = (uint32_t)(((kc * 2 + lsel) ^ lx7) * 16);
            uint32_t ah[4], al_[4];
            ldsm4(ah, ah_b + (uint32_t)arow * ROWB + achunk);
            ldsm4(al_, al_b + (uint32_t)arow * ROWB + achunk);
#pragma unroll
            for (int nh = 0; nh < 2; nh++) {
#pragma unroll
                for (int t = 0; t < 2; t++) {
                    int n00 = nh * 32 + t * 16;
                    uint32_t brow = (uint32_t)(n00 + lrow);
                    uint32_t boff = brow * ROWB + (uint32_t)(((kc * 2 + lsel) ^ (brow & 7)) * 16);
                    uint32_t bh[4];
                    ldsm4(bh, bcur + boff);
                    int nb = nh * 4 + t * 2;
                    mma_f16(sacc[nb],     ah,  bh[0], bh[2]);
                    mma_f16(sacc[nb + 1], ah,  bh[1], bh[3]);
                    mma_f16(sacc[nb],     al_, bh[0], bh[2]);
                    mma_f16(sacc[nb + 1], al_, bh[1], bh[3]);
                }
            }
        }

        // ---- weight epilogue: S -> w (fp16 hi/lo A-fragments, in regs) ----
        uint32_t wh[4][4], wl[4][4];
#pragma unroll
        for (int nb = 0; nb < 8; nb++) {
            int jp = j0 + nb * 8 + 2 * qp;
            float2 aj0 = __ldg((const float2*)(adj + (size_t)gi0 * NN + jp));
            float2 aj8 = __ldg((const float2*)(adj + (size_t)(gi0 + 8) * NN + jp));
            float2 rj = __ldg((const float2*)(rvec + jp));

            float ww[4];
            float sv[4] = {sacc[nb][0], sacc[nb][1], sacc[nb][2], sacc[nb][3]};
            float av[4] = {aj0.x, aj0.y, aj8.x, aj8.y};
            float rv[4] = {rj.x, rj.y, rj.x, rj.y};
            float riv[4] = {ri0, ri0, ri8, ri8};
            float div_[4] = {di0, di0, di8, di8};
            int giv[4] = {gi0, gi0, gi0 + 8, gi0 + 8};
            int gjv[4] = {jp, jp + 1, jp, jp + 1};
#pragma unroll
            for (int u = 0; u < 4; u++) {
                float a = av[u];
                float am = fmaxf(a, EPSV);
                float z = dc0 * (div_[u] * __frcp_rn(am) - 1.f) + dc1;
                float sp = softplusf(z);
                float e = sv[u] * __frcp_rn(fmaxf(riv[u] * rv[u], EPSV));
                float att = e * a * sp;
                if (giv[u] == gjv[u]) att = 0.f;
                ww[u] = (att > 0.f ? c0 : c1) * att;
            }
            int kc = nb >> 1, o = (nb & 1) * 2;
            pack_hl(ww[0], ww[1], wh[kc][o], wl[kc][o]);
            pack_hl(ww[2], ww[3], wh[kc][o + 1], wl[kc][o + 1]);
        }

        // ---- propagate: P += w @ Whj (B via ldmatrix.trans), split-w x2 ----
#pragma unroll
        for (int kc = 0; kc < 4; kc++) {
            uint32_t jrow = (uint32_t)(kc * 16 + lrow);
#pragma unroll
            for (int dt = 0; dt < D / 16; dt++) {
                uint32_t boff = jrow * ROWB + (uint32_t)(((dt * 2 + lsel) ^ (jrow & 7)) * 16);
                uint32_t bh[4];
                ldsm4t(bh, bcur + boff);
                int p0 = dt * 2, p1 = dt * 2 + 1;
                mma_f16(pacc[p0], wh[kc], bh[0], bh[1]);
                mma_f16(pacc[p1], wh[kc], bh[2], bh[3]);
                mma_f16(pacc[p0], wl[kc], bh[0], bh[1]);
                mma_f16(pacc[p1], wl[kc], bh[2], bh[3]);
            }
        }
    }

    // ---- writeout ----
    float* dst0 = part + ((size_t)blockIdx.y * NN + gi0) * D;
    float* dst8 = dst0 + 8 * (size_t)D;
#pragma unroll
    for (int q = 0; q < DNB; q++) {
        int d = q * 8 + 2 * qp;
        *(float2*)(dst0 + d) = make_float2(pacc[q][0], pacc[q][1]);
        *(float2*)(dst8 + d) = make_float2(pacc[q][2], pacc[q][3]);
    }
}

// ---------------- epilogue layers 0..2 ----------------
__global__ void epi_kernel(const float* __restrict__ part, const float* __restrict__ Wh,
                           float* __restrict__ prev,
                           const float* __restrict__ cf, const float* __restrict__ sp,
                           float coeff) {
    int idx = blockIdx.x * 256 + threadIdx.x;
    float f0 = __ldg(cf), f1 = __ldg(cf + 1), f2 = __ldg(cf + 2);
    float mxc = fmaxf(f0, fmaxf(f1, f2));
    float e0 = __expf(f0 - mxc), e1 = __expf(f1 - mxc), e2 = __expf(f2 - mxc);
    float c2 = e2 / (e0 + e1 + e2);
    float s = softplusf(__ldg(sp));
    const size_t ST = (size_t)NN * 256;
    float psum = part[idx] + part[ST + idx] + part[2 * ST + idx] + part[3 * ST + idx];
    float inner = s * (psum + c2 * Wh[idx]);
    prev[idx] += coeff * eluf(inner);
}

// ---------------- final: log_softmax over 16 classes (part stride 64) --------
__global__ void final_kernel(const float* __restrict__ part, const float* __restrict__ Wh,
                             const float* __restrict__ cf, const float* __restrict__ sp,
                             float* __restrict__ out) {
    int row = blockIdx.x * blockDim.x + threadIdx.x;
    float f0 = __ldg(cf), f1 = __ldg(cf + 1), f2 = __ldg(cf + 2);
    float mxc = fmaxf(f0, fmaxf(f1, f2));
    float e0 = __expf(f0 - mxc), e1 = __expf(f1 - mxc), e2 = __expf(f2 - mxc);
    float c2 = e2 / (e0 + e1 + e2);
    float s = softplusf(__ldg(sp));
    const size_t ST = (size_t)NN * 64;

    float v[16];
    float mx = -3.4e38f;
#pragma unroll
    for (int c = 0; c < 16; c++) {
        size_t o = (size_t)row * 64 + c;
        float psum = part[o] + part[ST + o] + part[2 * ST + o] + part[3 * ST + o];
        float t = s * (psum + c2 * Wh[(size_t)row * 64 + c]);
        v[c] = t;
        mx = fmaxf(mx, t);
    }
    float lse = 0.f;
#pragma unroll
    for (int c = 0; c < 16; c++) lse += expf(v[c] - mx);
    lse = logf(lse);
#pragma unroll
    for (int c = 0; c < 16; c++) out[row * 16 + c] = v[c] - mx - lse;
}

// ---------------- host launcher ----------------
extern "C" void kernel_launch(void* const* d_in, const int* in_sizes, int n_in,
                              void* d_out, int out_size) {
    const float* x   = (const float*)d_in[0];
    const float* adj = (const float*)d_in[1];
    const float* Wf  = (const float*)d_in[2];
    const float* bf  = (const float*)d_in[3];
    const float* W0  = (const float*)d_in[4];
    const float* b0  = (const float*)d_in[5];
    const float* W1  = (const float*)d_in[6];
    const float* b1  = (const float*)d_in[7];
    const float* W2  = (const float*)d_in[8];
    const float* b2  = (const float*)d_in[9];
    const float* W3  = (const float*)d_in[10];
    const float* b3  = (const float*)d_in[11];
    const float* dcs = (const float*)d_in[12];
    const float* cfs = (const float*)d_in[13];
    const float* sps = (const float*)d_in[14];
    float* out = (float*)d_out;

    float *p_prev, *p_Wh, *p_part, *p_diag, *p_r;
    __half *p_WhH, *p_WhL;
    cudaGetSymbolAddress((void**)&p_prev, g_prev);
    cudaGetSymbolAddress((void**)&p_Wh, g_Wh);
    cudaGetSymbolAddress((void**)&p_part, g_part);
    cudaGetSymbolAddress((void**)&p_diag, g_diag);
    cudaGetSymbolAddress((void**)&p_r, g_r);
    cudaGetSymbolAddress((void**)&p_WhH, g_WhH);
    cudaGetSymbolAddress((void**)&p_WhL, g_WhL);

    const int SM256 = (2 * 128 + 2 * 64) * 2 * 256;  // 196608 B
    const int SM64  = (2 * 128 + 2 * 64) * 2 * 64;   //  49152 B
    cudaFuncSetAttribute(fused_mma<256>, cudaFuncAttributeMaxDynamicSharedMemorySize, SM256);
    cudaFuncSetAttribute(fused_mma<64>,  cudaFuncAttributeMaxDynamicSharedMemorySize, SM64);

    const float cI1 = 1.0f;
    const float cI2 = logf(1.0f / 27.0f + 1.0f);
    const float cI3 = logf(1.0f / 64.0f + 1.0f);

    diag_kernel<<<NN / 256, 256>>>(adj, p_diag);
    gemm_bias_kernel<<<dim3(64, 4), 256>>>(x, Wf, bf, p_prev, 512, 1);

    // ---- layer 0 ----
    gemm_bias_kernel<<<dim3(64, 4), 256>>>(x, W0, b0, p_Wh, 512, 0);
    rownorm_kernel<<<512, 256>>>(p_Wh, p_r, 256);
    cvt_kernel<256><<<512, 256>>>(p_Wh, p_WhH, p_WhL);
    fused_mma<256><<<dim3(32, 4), 256, SM256>>>(p_WhH, p_WhL, p_r, p_diag, adj,
                                                dcs + 0, cfs + 0, p_part);
    epi_kernel<<<NN, 256>>>(p_part, p_Wh, p_prev, cfs + 0, sps + 0, cI1);

    // ---- layer 1 ----
    gemm_bias_kernel<<<dim3(64, 4), 256>>>(p_prev, W1, b1, p_Wh, 256, 0);
    rownorm_kernel<<<512, 256>>>(p_Wh, p_r, 256);
    cvt_kernel<256><<<512, 256>>>(p_Wh, p_WhH, p_WhL);
    fused_mma<256><<<dim3(32, 4), 256, SM256>>>(p_WhH, p_WhL, p_r, p_diag, adj,
                                                dcs + 2, cfs + 3, p_part);
    epi_kernel<<<NN, 256>>>(p_part, p_Wh, p_prev, cfs + 3, sps + 1, cI2);

    // ---- layer 2 ----
    gemm_bias_kernel<<<dim3(64, 4), 256>>>(p_prev, W2, b2, p_Wh, 256, 0);
    rownorm_kernel<<<512, 256>>>(p_Wh, p_r, 256);
    cvt_kernel<256><<<512, 256>>>(p_Wh, p_WhH, p_WhL);
    fused_mma<256><<<dim3(32, 4), 256, SM256>>>(p_WhH, p_WhL, p_r, p_diag, adj,
                                                dcs + 4, cfs + 6, p_part);
    epi_kernel<<<NN, 256>>>(p_part, p_Wh, p_prev, cfs + 6, sps + 2, cI3);

    // ---- layer 3 (D=16 zero-padded to 64) ----
    wh16_kernel<<<NN * 64 / 256, 256>>>(p_prev, W3, b3, p_Wh);
    rownorm_kernel<<<512, 256>>>(p_Wh, p_r, 64);
    cvt_kernel<64><<<128, 256>>>(p_Wh, p_WhH, p_WhL);
    fused_mma<64><<<dim3(32, 4), 256, SM64>>>(p_WhH, p_WhL, p_r, p_diag, adj,
                                              dcs + 6, cfs + 9, p_part);
    final_kernel<<<NN / 256, 256>>>(p_part, p_Wh, cfs + 9, sps + 3, out);
}

// round 7
// speedup vs baseline: 3.5600x; 1.2493x over previous
#include <cuda_runtime.h>
#include <cuda_fp16.h>
#include <math.h>
#include <stdint.h>

#define NN 4096
#define EPSV 1e-9f

// ---------------- device scratch (static, allocation-free) ----------------
__device__ float g_prev[NN * 256];
__device__ float g_Wh[NN * 256];
__device__ float g_part[4 * NN * 256];   // 4-way j-split partial propagate sums
__device__ float g_diag[NN];
__device__ float g_r[NN];
__device__ __half g_WhH[NN * 256];       // Wh fp16, swizzled chunks

// ---------------- asm helpers ----------------
__device__ __forceinline__ uint32_t smem_u32(const void* p) {
    return (uint32_t)__cvta_generic_to_shared((void*)p);
}
__device__ __forceinline__ void ldsm4(uint32_t* r, uint32_t addr) {
    asm volatile("ldmatrix.sync.aligned.m8n8.x4.shared.b16 {%0,%1,%2,%3}, [%4];"
                 : "=r"(r[0]), "=r"(r[1]), "=r"(r[2]), "=r"(r[3]) : "r"(addr));
}
__device__ __forceinline__ void ldsm4t(uint32_t* r, uint32_t addr) {
    asm volatile("ldmatrix.sync.aligned.m8n8.x4.trans.shared.b16 {%0,%1,%2,%3}, [%4];"
                 : "=r"(r[0]), "=r"(r[1]), "=r"(r[2]), "=r"(r[3]) : "r"(addr));
}
__device__ __forceinline__ void mma_f16(float* c, const uint32_t* a, uint32_t b0, uint32_t b1) {
    asm volatile("mma.sync.aligned.m16n8k16.row.col.f32.f16.f16.f32 "
                 "{%0,%1,%2,%3}, {%4,%5,%6,%7}, {%8,%9}, {%0,%1,%2,%3};"
                 : "+f"(c[0]), "+f"(c[1]), "+f"(c[2]), "+f"(c[3])
                 : "r"(a[0]), "r"(a[1]), "r"(a[2]), "r"(a[3]), "r"(b0), "r"(b1));
}
__device__ __forceinline__ void cp16(uint32_t dst, const void* src) {
    asm volatile("cp.async.cg.shared.global [%0], [%1], 16;" :: "r"(dst), "l"(src));
}
#define CP_COMMIT() asm volatile("cp.async.commit_group;" ::: "memory")

// ---------------- math helpers ----------------
__device__ __forceinline__ float softplusf(float z) {
    return (z > 15.f) ? z : __logf(1.f + __expf(z));
}
__device__ __forceinline__ float eluf(float x) { return x > 0.f ? x : expm1f(x); }

__device__ __forceinline__ void fma16(float (&p)[4][4], float4 a, float4 b) {
    p[0][0] += a.x * b.x; p[0][1] += a.x * b.y; p[0][2] += a.x * b.z; p[0][3] += a.x * b.w;
    p[1][0] += a.y * b.x; p[1][1] += a.y * b.y; p[1][2] += a.y * b.z; p[1][3] += a.y * b.w;
    p[2][0] += a.z * b.x; p[2][1] += a.z * b.y; p[2][2] += a.z * b.z; p[2][3] += a.z * b.w;
    p[3][0] += a.w * b.x; p[3][1] += a.w * b.y; p[3][2] += a.w * b.z; p[3][3] += a.w * b.w;
}

__device__ __forceinline__ uint32_t pack_h(float a, float b) {
    __half2 h = __floats2half2_rn(a, b);
    return *(uint32_t*)&h;
}

// ---------------- Wh fp32 -> swizzled fp16 global array ----------------
// chunk layout: elem16 offset = row*D + (c ^ (row&7))*8 + (k&7), c = k>>3.
template <int D>
__global__ void cvt_kernel(const float* __restrict__ src, __half* __restrict__ H) {
    int idx = blockIdx.x * 256 + threadIdx.x;   // NN*D/8 chunks
    int row = idx / (D / 8);
    int c = idx % (D / 8);
    const float* s = src + (size_t)row * D + c * 8;
    float4 v0 = __ldg((const float4*)s);
    float4 v1 = __ldg((const float4*)(s + 4));
    int dcn = c ^ (row & 7);
    size_t off = (size_t)row * D + dcn * 8;
    __half2 h0 = __floats2half2_rn(v0.x, v0.y), h1 = __floats2half2_rn(v0.z, v0.w);
    __half2 h2 = __floats2half2_rn(v1.x, v1.y), h3 = __floats2half2_rn(v1.z, v1.w);
    *(uint4*)(H + off) = make_uint4(*(uint32_t*)&h0, *(uint32_t*)&h1,
                                    *(uint32_t*)&h2, *(uint32_t*)&h3);
}

// ---------------- small kernels ----------------
__global__ void diag_kernel(const float* __restrict__ adj, float* __restrict__ dg) {
    int i = blockIdx.x * 256 + threadIdx.x;
    dg[i] = adj[(size_t)i * (NN + 1)];
}

__global__ __launch_bounds__(256)
void gemm_bias_kernel(const float* __restrict__ A, const float* __restrict__ W,
                      const float* __restrict__ bias, float* __restrict__ C,
                      int K, int do_elu) {
    __shared__ float sA[16][68];
    __shared__ float sB[16][68];
    const int tid = threadIdx.x;
    const int ty = tid >> 4, tx = tid & 15;
    const int i0 = blockIdx.x * 64, j0 = blockIdx.y * 64;
    const int mload = tid >> 4;
    const int kload = tid & 15;
    const int kload2 = tid >> 6;
    const int nload = tid & 63;

    float p[4][4];
#pragma unroll
    for (int u = 0; u < 4; u++)
#pragma unroll
        for (int v = 0; v < 4; v++) p[u][v] = 0.f;

    for (int kb = 0; kb < K; kb += 16) {
        __syncthreads();
#pragma unroll
        for (int r = 0; r < 4; r++)
            sA[kload][mload + 16 * r] = A[(size_t)(i0 + mload + 16 * r) * K + kb + kload];
#pragma unroll
        for (int r = 0; r < 4; r++)
            sB[kload2 + 4 * r][nload] = W[(size_t)(kb + kload2 + 4 * r) * 256 + j0 + nload];
        __syncthreads();
#pragma unroll
        for (int kk = 0; kk < 16; kk++) {
            float4 a = *(const float4*)&sA[kk][4 * ty];
            float4 b = *(const float4*)&sB[kk][4 * tx];
            fma16(p, a, b);
        }
    }
#pragma unroll
    for (int u = 0; u < 4; u++) {
#pragma unroll
        for (int v = 0; v < 4; v++) {
            float val = p[u][v] + __ldg(bias + j0 + 4 * tx + v);
            if (do_elu) val = eluf(val);
            C[(size_t)(i0 + 4 * ty + u) * 256 + j0 + 4 * tx + v] = val;
        }
    }
}

// layer 3: Wh64 = zero-pad(prev @ W3 + b3) to [N,64]
__global__ void wh16_kernel(const float* __restrict__ H, const float* __restrict__ W3,
                            const float* __restrict__ b3, float* __restrict__ Wh) {
    int idx = blockIdx.x * 256 + threadIdx.x;  // NN*64
    int i = idx >> 6, c = idx & 63;
    float s = 0.f;
    if (c < 16) {
        s = __ldg(b3 + c);
        const float* h = H + (size_t)i * 256;
#pragma unroll 8
        for (int k = 0; k < 256; k++) s += h[k] * __ldg(W3 + k * 16 + c);
    }
    Wh[idx] = s;
}

__global__ void rownorm_kernel(const float* __restrict__ Wh, float* __restrict__ r, int D) {
    int row = blockIdx.x * 8 + (threadIdx.x >> 5);
    int lane = threadIdx.x & 31;
    float s = 0.f;
    for (int k = lane; k < D; k += 32) {
        float v = Wh[(size_t)row * D + k];
        s += v * v;
    }
#pragma unroll
    for (int o = 16; o; o >>= 1) s += __shfl_xor_sync(0xffffffffu, s, o);
    if (lane == 0) r[row] = sqrtf(s);
}

// ---------------- fused mma.sync attention layer (single fp16) ----------------
// grid (32, 4): 128-row i tiles x 4-way j split; 256 threads, 8 warps over i.
// SMEM: Ah[128xD] fp16 + B double buffer (2 x 64xD fp16) + adj tile [128][68] f32.
template <int D>  // 256, or 64 (layer 3 zero-padded)
__global__ __launch_bounds__(256, 1)
void fused_mma(const __half* __restrict__ WhH,
               const float* __restrict__ rvec,
               const float* __restrict__ diagv, const float* __restrict__ adj,
               const float* __restrict__ dc, const float* __restrict__ cf,
               float* __restrict__ part) {
    constexpr int KCH = D / 16;   // score k-chunks
    constexpr int DNB = D / 8;    // propagate n-blocks (P accumulators)
    constexpr int ROWB = 2 * D;   // smem row bytes (fp16)
    constexpr int BBYTES = 64 * ROWB;
    constexpr int APITCH = 68;    // adj smem pitch (floats)

    extern __shared__ char sm[];
    char* Ah = sm;
    char* Bb = sm + 128 * ROWB;
    float* adjS = (float*)(sm + 128 * ROWB + 2 * BBYTES);
    const uint32_t ah_b = smem_u32(Ah);
    const uint32_t bb_b = smem_u32(Bb);
    const uint32_t adj_b = smem_u32(adjS);

    const int tid = threadIdx.x;
    const int w = tid >> 5, lane = tid & 31;
    const int i0 = blockIdx.x * 128;
    const int jbase = blockIdx.y * (NN / 4);
    const int row0 = lane >> 2;
    const int qp = lane & 3;
    const int gi0 = i0 + w * 16 + row0;

    const int lrow = lane & 15;
    const int lsel = lane >> 4;
    const int lx7 = lane & 7;

    // per-layer scalars
    float dc0 = __ldg(dc), dc1 = __ldg(dc + 1);
    float f0 = __ldg(cf), f1 = __ldg(cf + 1), f2 = __ldg(cf + 2);
    float mxc = fmaxf(f0, fmaxf(f1, f2));
    float e0 = __expf(f0 - mxc), e1 = __expf(f1 - mxc), e2 = __expf(f2 - mxc);
    float inv = 1.f / (e0 + e1 + e2);
    float c0 = e0 * inv, c1 = e1 * inv;
    float ri0 = __ldg(rvec + gi0), ri8 = __ldg(rvec + gi0 + 8);
    float di0 = __ldg(diagv + gi0), di8 = __ldg(diagv + gi0 + 8);

    // A tile: raw copy (swizzle preserved: i0 multiple of 128 keeps row mod 8)
    {
        const uint4* gH = (const uint4*)(WhH + (size_t)i0 * D);
        uint4* sH = (uint4*)Ah;
#pragma unroll 4
        for (int it = tid; it < 16 * D; it += 256) sH[it] = __ldg(gH + it);
    }

    // prefetch B tile 0 into buffer 0
    {
        const char* src = (const char*)(WhH + (size_t)jbase * D);
        for (int off = tid * 16; off < BBYTES; off += 4096) cp16(bb_b + off, src + off);
        CP_COMMIT();
    }

    float pacc[DNB][4];
#pragma unroll
    for (int q = 0; q < DNB; q++)
#pragma unroll
        for (int v = 0; v < 4; v++) pacc[q][v] = 0.f;

    const int arow = w * 16 + lrow;
    const int ra = w * 16 + row0;

    for (int tt = 0; tt < 16; tt++) {
        int j0 = jbase + tt * 64;
        __syncthreads();   // prop(tt-1) done reading B[(tt+1)&1] and adjS

        // adj[tt] tile prefetch: 128 rows x 64 cols f32 (2048 x 16B chunks)
        {
            const char* asrc = (const char*)(adj + (size_t)i0 * NN + j0);
#pragma unroll
            for (int k = 0; k < 8; k++) {
                int idx = tid + k * 256;
                int row = idx >> 4, ch = idx & 15;
                cp16(adj_b + row * 272 + ch * 16, asrc + (size_t)row * (NN * 4) + ch * 16);
            }
            CP_COMMIT();
        }
        if (tt + 1 < 16) {   // B[tt+1] prefetch
            const char* src = (const char*)(WhH + (size_t)(j0 + 64) * D);
            uint32_t dst = bb_b + ((tt + 1) & 1) * BBYTES;
            for (int off = tid * 16; off < BBYTES; off += 4096) cp16(dst + off, src + off);
            CP_COMMIT();
            asm volatile("cp.async.wait_group 2;" ::: "memory");  // B[tt] done
        } else {
            asm volatile("cp.async.wait_group 1;" ::: "memory");  // B[tt] done
        }
        __syncthreads();
        const uint32_t bcur = bb_b + (tt & 1) * BBYTES;

        // ---- score: S[16x64] per warp, single fp16 ----
        float sacc[8][4];
#pragma unroll
        for (int q = 0; q < 8; q++)
#pragma unroll
            for (int v = 0; v < 4; v++) sacc[q][v] = 0.f;

#pragma unroll
        for (int kc = 0; kc < KCH; kc++) {
            uint32_t achunk = (uint32_t)(((kc * 2 + lsel) ^ lx7) * 16);
            uint32_t ah[4];
            ldsm4(ah, ah_b + (uint32_t)arow * ROWB + achunk);
#pragma unroll
            for (int nh = 0; nh < 2; nh++) {
#pragma unroll
                for (int t = 0; t < 2; t++) {
                    int n00 = nh * 32 + t * 16;
                    uint32_t brow = (uint32_t)(n00 + lrow);
                    uint32_t boff = brow * ROWB + (uint32_t)(((kc * 2 + lsel) ^ (brow & 7)) * 16);
                    uint32_t bh[4];
                    ldsm4(bh, bcur + boff);
                    int nb = nh * 4 + t * 2;
                    mma_f16(sacc[nb],     ah, bh[0], bh[2]);
                    mma_f16(sacc[nb + 1], ah, bh[1], bh[3]);
                }
            }
        }

        // adj[tt] now needed
        if (tt + 1 < 16) {
            asm volatile("cp.async.wait_group 1;" ::: "memory");
        } else {
            asm volatile("cp.async.wait_group 0;" ::: "memory");
        }
        __syncthreads();

        // ---- weight epilogue: S -> w (fp16 A-fragments, in regs) ----
        uint32_t wh[4][4];
#pragma unroll
        for (int nb = 0; nb < 8; nb++) {
            int jp = j0 + nb * 8 + 2 * qp;
            int col = nb * 8 + 2 * qp;
            float2 a0 = *(const float2*)(adjS + ra * APITCH + col);
            float2 a8 = *(const float2*)(adjS + (ra + 8) * APITCH + col);
            float2 rj = __ldg((const float2*)(rvec + jp));

            float ww[4];
            float sv[4] = {sacc[nb][0], sacc[nb][1], sacc[nb][2], sacc[nb][3]};
            float av[4] = {a0.x, a0.y, a8.x, a8.y};
            float rv[4] = {rj.x, rj.y, rj.x, rj.y};
            float riv[4] = {ri0, ri0, ri8, ri8};
            float div_[4] = {di0, di0, di8, di8};
            int giv[4] = {gi0, gi0, gi0 + 8, gi0 + 8};
            int gjv[4] = {jp, jp + 1, jp, jp + 1};
#pragma unroll
            for (int u = 0; u < 4; u++) {
                float a = av[u];
                float am = fmaxf(a, EPSV);
                float z = dc0 * (div_[u] * __frcp_rn(am) - 1.f) + dc1;
                float sp = softplusf(z);
                float e = sv[u] * __frcp_rn(fmaxf(riv[u] * rv[u], EPSV));
                float att = e * a * sp;
                if (giv[u] == gjv[u]) att = 0.f;
                ww[u] = (att > 0.f ? c0 : c1) * att;
            }
            int kc = nb >> 1, o = (nb & 1) * 2;
            wh[kc][o] = pack_h(ww[0], ww[1]);
            wh[kc][o + 1] = pack_h(ww[2], ww[3]);
        }

        // ---- propagate: P += w @ Whj (B via ldmatrix.trans), single fp16 ----
#pragma unroll
        for (int kc = 0; kc < 4; kc++) {
            uint32_t jrow = (uint32_t)(kc * 16 + lrow);
#pragma unroll
            for (int dt = 0; dt < D / 16; dt++) {
                uint32_t boff = jrow * ROWB + (uint32_t)(((dt * 2 + lsel) ^ (jrow & 7)) * 16);
                uint32_t bh[4];
                ldsm4t(bh, bcur + boff);
                int p0 = dt * 2, p1 = dt * 2 + 1;
                mma_f16(pacc[p0], wh[kc], bh[0], bh[1]);
                mma_f16(pacc[p1], wh[kc], bh[2], bh[3]);
            }
        }
    }

    // ---- writeout ----
    float* dst0 = part + ((size_t)blockIdx.y * NN + gi0) * D;
    float* dst8 = dst0 + 8 * (size_t)D;
#pragma unroll
    for (int q = 0; q < DNB; q++) {
        int d = q * 8 + 2 * qp;
        *(float2*)(dst0 + d) = make_float2(pacc[q][0], pacc[q][1]);
        *(float2*)(dst8 + d) = make_float2(pacc[q][2], pacc[q][3]);
    }
}

// ---------------- epilogue layers 0..2 ----------------
__global__ void epi_kernel(const float* __restrict__ part, const float* __restrict__ Wh,
                           float* __restrict__ prev,
                           const float* __restrict__ cf, const float* __restrict__ sp,
                           float coeff) {
    int idx = blockIdx.x * 256 + threadIdx.x;
    float f0 = __ldg(cf), f1 = __ldg(cf + 1), f2 = __ldg(cf + 2);
    float mxc = fmaxf(f0, fmaxf(f1, f2));
    float e0 = __expf(f0 - mxc), e1 = __expf(f1 - mxc), e2 = __expf(f2 - mxc);
    float c2 = e2 / (e0 + e1 + e2);
    float s = softplusf(__ldg(sp));
    const size_t ST = (size_t)NN * 256;
    float psum = part[idx] + part[ST + idx] + part[2 * ST + idx] + part[3 * ST + idx];
    float inner = s * (psum + c2 * Wh[idx]);
    prev[idx] += coeff * eluf(inner);
}

// ---------------- final: log_softmax over 16 classes (part stride 64) --------
__global__ void final_kernel(const float* __restrict__ part, const float* __restrict__ Wh,
                             const float* __restrict__ cf, const float* __restrict__ sp,
                             float* __restrict__ out) {
    int row = blockIdx.x * blockDim.x + threadIdx.x;
    float f0 = __ldg(cf), f1 = __ldg(cf + 1), f2 = __ldg(cf + 2);
    float mxc = fmaxf(f0, fmaxf(f1, f2));
    float e0 = __expf(f0 - mxc), e1 = __expf(f1 - mxc), e2 = __expf(f2 - mxc);
    float c2 = e2 / (e0 + e1 + e2);
    float s = softplusf(__ldg(sp));
    const size_t ST = (size_t)NN * 64;

    float v[16];
    float mx = -3.4e38f;
#pragma unroll
    for (int c = 0; c < 16; c++) {
        size_t o = (size_t)row * 64 + c;
        float psum = part[o] + part[ST + o] + part[2 * ST + o] + part[3 * ST + o];
        float t = s * (psum + c2 * Wh[(size_t)row * 64 + c]);
        v[c] = t;
        mx = fmaxf(mx, t);
    }
    float lse = 0.f;
#pragma unroll
    for (int c = 0; c < 16; c++) lse += expf(v[c] - mx);
    lse = logf(lse);
#pragma unroll
    for (int c = 0; c < 16; c++) out[row * 16 + c] = v[c] - mx - lse;
}

// ---------------- host launcher ----------------
extern "C" void kernel_launch(void* const* d_in, const int* in_sizes, int n_in,
                              void* d_out, int out_size) {
    const float* x   = (const float*)d_in[0];
    const float* adj = (const float*)d_in[1];
    const float* Wf  = (const float*)d_in[2];
    const float* bf  = (const float*)d_in[3];
    const float* W0  = (const float*)d_in[4];
    const float* b0  = (const float*)d_in[5];
    const float* W1  = (const float*)d_in[6];
    const float* b1  = (const float*)d_in[7];
    const float* W2  = (const float*)d_in[8];
    const float* b2  = (const float*)d_in[9];
    const float* W3  = (const float*)d_in[10];
    const float* b3  = (const float*)d_in[11];
    const float* dcs = (const float*)d_in[12];
    const float* cfs = (const float*)d_in[13];
    const float* sps = (const float*)d_in[14];
    float* out = (float*)d_out;

    float *p_prev, *p_Wh, *p_part, *p_diag, *p_r;
    __half *p_WhH;
    cudaGetSymbolAddress((void**)&p_prev, g_prev);
    cudaGetSymbolAddress((void**)&p_Wh, g_Wh);
    cudaGetSymbolAddress((void**)&p_part, g_part);
    cudaGetSymbolAddress((void**)&p_diag, g_diag);
    cudaGetSymbolAddress((void**)&p_r, g_r);
    cudaGetSymbolAddress((void**)&p_WhH, g_WhH);

    // smem: A + 2xB + adj[128][68]
    const int SM256 = 128 * 512 + 2 * 32768 + 128 * 68 * 4;  // 165888
    const int SM64  = 128 * 128 + 2 * 8192 + 128 * 68 * 4;   //  67584
    cudaFuncSetAttribute(fused_mma<256>, cudaFuncAttributeMaxDynamicSharedMemorySize, SM256);
    cudaFuncSetAttribute(fused_mma<64>,  cudaFuncAttributeMaxDynamicSharedMemorySize, SM64);

    const float cI1 = 1.0f;
    const float cI2 = logf(1.0f / 27.0f + 1.0f);
    const float cI3 = logf(1.0f / 64.0f + 1.0f);

    diag_kernel<<<NN / 256, 256>>>(adj, p_diag);
    gemm_bias_kernel<<<dim3(64, 4), 256>>>(x, Wf, bf, p_prev, 512, 1);

    // ---- layer 0 ----
    gemm_bias_kernel<<<dim3(64, 4), 256>>>(x, W0, b0, p_Wh, 512, 0);
    rownorm_kernel<<<512, 256>>>(p_Wh, p_r, 256);
    cvt_kernel<256><<<512, 256>>>(p_Wh, p_WhH);
    fused_mma<256><<<dim3(32, 4), 256, SM256>>>(p_WhH, p_r, p_diag, adj,
                                                dcs + 0, cfs + 0, p_part);
    epi_kernel<<<NN, 256>>>(p_part, p_Wh, p_prev, cfs + 0, sps + 0, cI1);

    // ---- layer 1 ----
    gemm_bias_kernel<<<dim3(64, 4), 256>>>(p_prev, W1, b1, p_Wh, 256, 0);
    rownorm_kernel<<<512, 256>>>(p_Wh, p_r, 256);
    cvt_kernel<256><<<512, 256>>>(p_Wh, p_WhH);
    fused_mma<256><<<dim3(32, 4), 256, SM256>>>(p_WhH, p_r, p_diag, adj,
                                                dcs + 2, cfs + 3, p_part);
    epi_kernel<<<NN, 256>>>(p_part, p_Wh, p_prev, cfs + 3, sps + 1, cI2);

    // ---- layer 2 ----
    gemm_bias_kernel<<<dim3(64, 4), 256>>>(p_prev, W2, b2, p_Wh, 256, 0);
    rownorm_kernel<<<512, 256>>>(p_Wh, p_r, 256);
    cvt_kernel<256><<<512, 256>>>(p_Wh, p_WhH);
    fused_mma<256><<<dim3(32, 4), 256, SM256>>>(p_WhH, p_r, p_diag, adj,
                                                dcs + 4, cfs + 6, p_part);
    epi_kernel<<<NN, 256>>>(p_part, p_Wh, p_prev, cfs + 6, sps + 2, cI3);

    // ---- layer 3 (D=16 zero-padded to 64) ----
    wh16_kernel<<<NN * 64 / 256, 256>>>(p_prev, W3, b3, p_Wh);
    rownorm_kernel<<<512, 256>>>(p_Wh, p_r, 64);
    cvt_kernel<64><<<128, 256>>>(p_Wh, p_WhH);
    fused_mma<64><<<dim3(32, 4), 256, SM64>>>(p_WhH, p_r, p_diag, adj,
                                              dcs + 6, cfs + 9, p_part);
    final_kernel<<<NN / 256, 256>>>(p_part, p_Wh, cfs + 9, sps + 3, out);
}

// round 8
// speedup vs baseline: 4.4168x; 1.2407x over previous
#include <cuda_runtime.h>
#include <cuda_fp16.h>
#include <math.h>
#include <stdint.h>

#define NN 4096
#define EPSV 1e-9f

// ---------------- device scratch (static, allocation-free) ----------------
__device__ float g_prev[NN * 256];
__device__ float g_Wh[NN * 256];
__device__ float g_part[4 * NN * 256];   // 4-way j-split partial propagate sums
__device__ float g_diag[NN];
__device__ float g_rinv[NN];             // 1 / ||Wh_i||
__device__ __half g_WhH[NN * 256];       // Wh fp16, swizzled chunks

// ---------------- asm helpers ----------------
__device__ __forceinline__ uint32_t smem_u32(const void* p) {
    return (uint32_t)__cvta_generic_to_shared((void*)p);
}
__device__ __forceinline__ void ldsm4(uint32_t* r, uint32_t addr) {
    asm volatile("ldmatrix.sync.aligned.m8n8.x4.shared.b16 {%0,%1,%2,%3}, [%4];"
                 : "=r"(r[0]), "=r"(r[1]), "=r"(r[2]), "=r"(r[3]) : "r"(addr));
}
__device__ __forceinline__ void ldsm4t(uint32_t* r, uint32_t addr) {
    asm volatile("ldmatrix.sync.aligned.m8n8.x4.trans.shared.b16 {%0,%1,%2,%3}, [%4];"
                 : "=r"(r[0]), "=r"(r[1]), "=r"(r[2]), "=r"(r[3]) : "r"(addr));
}
__device__ __forceinline__ void mma_f16(float* c, const uint32_t* a, uint32_t b0, uint32_t b1) {
    asm volatile("mma.sync.aligned.m16n8k16.row.col.f32.f16.f16.f32 "
                 "{%0,%1,%2,%3}, {%4,%5,%6,%7}, {%8,%9}, {%0,%1,%2,%3};"
                 : "+f"(c[0]), "+f"(c[1]), "+f"(c[2]), "+f"(c[3])
                 : "r"(a[0]), "r"(a[1]), "r"(a[2]), "r"(a[3]), "r"(b0), "r"(b1));
}
__device__ __forceinline__ void cp16(uint32_t dst, const void* src) {
    asm volatile("cp.async.cg.shared.global [%0], [%1], 16;" :: "r"(dst), "l"(src));
}
#define CP_COMMIT() asm volatile("cp.async.commit_group;" ::: "memory")

// ---------------- math helpers ----------------
__device__ __forceinline__ float softplusf(float z) {
    return (z > 15.f) ? z : __logf(1.f + __expf(z));
}
__device__ __forceinline__ float eluf(float x) { return x > 0.f ? x : expm1f(x); }

__device__ __forceinline__ void fma16(float (&p)[4][4], float4 a, float4 b) {
    p[0][0] += a.x * b.x; p[0][1] += a.x * b.y; p[0][2] += a.x * b.z; p[0][3] += a.x * b.w;
    p[1][0] += a.y * b.x; p[1][1] += a.y * b.y; p[1][2] += a.y * b.z; p[1][3] += a.y * b.w;
    p[2][0] += a.z * b.x; p[2][1] += a.z * b.y; p[2][2] += a.z * b.z; p[2][3] += a.z * b.w;
    p[3][0] += a.w * b.x; p[3][1] += a.w * b.y; p[3][2] += a.w * b.z; p[3][3] += a.w * b.w;
}

__device__ __forceinline__ uint32_t pack_h(float a, float b) {
    __half2 h = __floats2half2_rn(a, b);
    return *(uint32_t*)&h;
}

// ---------------- Wh fp32 -> swizzled fp16 global array ----------------
// chunk layout: elem16 offset = row*D + (c ^ (row&7))*8 + (k&7), c = k>>3.
template <int D>
__global__ void cvt_kernel(const float* __restrict__ src, __half* __restrict__ H) {
    int idx = blockIdx.x * 256 + threadIdx.x;   // NN*D/8 chunks
    int row = idx / (D / 8);
    int c = idx % (D / 8);
    const float* s = src + (size_t)row * D + c * 8;
    float4 v0 = __ldg((const float4*)s);
    float4 v1 = __ldg((const float4*)(s + 4));
    int dcn = c ^ (row & 7);
    size_t off = (size_t)row * D + dcn * 8;
    __half2 h0 = __floats2half2_rn(v0.x, v0.y), h1 = __floats2half2_rn(v0.z, v0.w);
    __half2 h2 = __floats2half2_rn(v1.x, v1.y), h3 = __floats2half2_rn(v1.z, v1.w);
    *(uint4*)(H + off) = make_uint4(*(uint32_t*)&h0, *(uint32_t*)&h1,
                                    *(uint32_t*)&h2, *(uint32_t*)&h3);
}

// ---------------- small kernels ----------------
__global__ void diag_kernel(const float* __restrict__ adj, float* __restrict__ dg) {
    int i = blockIdx.x * 256 + threadIdx.x;
    dg[i] = adj[(size_t)i * (NN + 1)];
}

__global__ __launch_bounds__(256)
void gemm_bias_kernel(const float* __restrict__ A, const float* __restrict__ W,
                      const float* __restrict__ bias, float* __restrict__ C,
                      int K, int do_elu) {
    __shared__ float sA[16][68];
    __shared__ float sB[16][68];
    const int tid = threadIdx.x;
    const int ty = tid >> 4, tx = tid & 15;
    const int i0 = blockIdx.x * 64, j0 = blockIdx.y * 64;
    const int mload = tid >> 4;
    const int kload = tid & 15;
    const int kload2 = tid >> 6;
    const int nload = tid & 63;

    float p[4][4];
#pragma unroll
    for (int u = 0; u < 4; u++)
#pragma unroll
        for (int v = 0; v < 4; v++) p[u][v] = 0.f;

    for (int kb = 0; kb < K; kb += 16) {
        __syncthreads();
#pragma unroll
        for (int r = 0; r < 4; r++)
            sA[kload][mload + 16 * r] = A[(size_t)(i0 + mload + 16 * r) * K + kb + kload];
#pragma unroll
        for (int r = 0; r < 4; r++)
            sB[kload2 + 4 * r][nload] = W[(size_t)(kb + kload2 + 4 * r) * 256 + j0 + nload];
        __syncthreads();
#pragma unroll
        for (int kk = 0; kk < 16; kk++) {
            float4 a = *(const float4*)&sA[kk][4 * ty];
            float4 b = *(const float4*)&sB[kk][4 * tx];
            fma16(p, a, b);
        }
    }
#pragma unroll
    for (int u = 0; u < 4; u++) {
#pragma unroll
        for (int v = 0; v < 4; v++) {
            float val = p[u][v] + __ldg(bias + j0 + 4 * tx + v);
            if (do_elu) val = eluf(val);
            C[(size_t)(i0 + 4 * ty + u) * 256 + j0 + 4 * tx + v] = val;
        }
    }
}

// layer 3: Wh64 = zero-pad(prev @ W3 + b3) to [N,64]
__global__ void wh16_kernel(const float* __restrict__ H, const float* __restrict__ W3,
                            const float* __restrict__ b3, float* __restrict__ Wh) {
    int idx = blockIdx.x * 256 + threadIdx.x;  // NN*64
    int i = idx >> 6, c = idx & 63;
    float s = 0.f;
    if (c < 16) {
        s = __ldg(b3 + c);
        const float* h = H + (size_t)i * 256;
#pragma unroll 8
        for (int k = 0; k < 256; k++) s += h[k] * __ldg(W3 + k * 16 + c);
    }
    Wh[idx] = s;
}

// outputs INVERSE row norm
__global__ void rownorm_kernel(const float* __restrict__ Wh, float* __restrict__ r, int D) {
    int row = blockIdx.x * 8 + (threadIdx.x >> 5);
    int lane = threadIdx.x & 31;
    float s = 0.f;
    for (int k = lane; k < D; k += 32) {
        float v = Wh[(size_t)row * D + k];
        s += v * v;
    }
#pragma unroll
    for (int o = 16; o; o >>= 1) s += __shfl_xor_sync(0xffffffffu, s, o);
    if (lane == 0) r[row] = 1.f / fmaxf(sqrtf(s), 1e-5f);
}

// ---------------- fused mma.sync attention layer (single fp16, BM=64) --------
// grid (64, 4): 64-row i tiles x 4-way j split; 128 threads, 4 warps over i.
// SMEM: Ah[64xD] fp16 + B double buffer (2 x 64xD fp16) + adj tile [64][64] f32
// (chunk-XOR swizzled). Sized for 2 CTAs/SM.
template <int D>  // 256, or 64 (layer 3 zero-padded)
__global__ __launch_bounds__(128)
void fused_mma(const __half* __restrict__ WhH,
               const float* __restrict__ rvec,
               const float* __restrict__ diagv, const float* __restrict__ adj,
               const float* __restrict__ dc, const float* __restrict__ cf,
               float* __restrict__ part) {
    constexpr int KCH = D / 16;   // score k-chunks
    constexpr int DNB = D / 8;    // propagate n-blocks (P accumulators)
    constexpr int ROWB = 2 * D;   // smem row bytes (fp16)
    constexpr int BBYTES = 64 * ROWB;

    extern __shared__ char sm[];
    char* Ah = sm;
    char* Bb = sm + 64 * ROWB;
    float* adjS = (float*)(sm + 64 * ROWB + 2 * BBYTES);
    const uint32_t ah_b = smem_u32(Ah);
    const uint32_t bb_b = smem_u32(Bb);
    const uint32_t adj_b = smem_u32(adjS);

    const int tid = threadIdx.x;
    const int w = tid >> 5, lane = tid & 31;  // 4 warps
    const int i0 = blockIdx.x * 64;
    const int jbase = blockIdx.y * (NN / 4);
    const int row0 = lane >> 2;
    const int qp = lane & 3;
    const int gi0 = i0 + w * 16 + row0;

    const int lrow = lane & 15;
    const int lsel = lane >> 4;
    const int lx7 = lane & 7;

    // per-layer scalars
    float dc0 = __ldg(dc), dc1 = __ldg(dc + 1);
    float f0 = __ldg(cf), f1 = __ldg(cf + 1), f2 = __ldg(cf + 2);
    float mxc = fmaxf(f0, fmaxf(f1, f2));
    float e0 = __expf(f0 - mxc), e1 = __expf(f1 - mxc), e2 = __expf(f2 - mxc);
    float inv = 1.f / (e0 + e1 + e2);
    float c0 = e0 * inv, c1 = e1 * inv;
    float ri0 = __ldg(rvec + gi0), ri8 = __ldg(rvec + gi0 + 8);   // inverse norms
    float di0 = __ldg(diagv + gi0), di8 = __ldg(diagv + gi0 + 8);

    // A tile: raw copy (swizzle preserved: i0 multiple of 64 keeps row mod 8)
    {
        const uint4* gH = (const uint4*)(WhH + (size_t)i0 * D);
        uint4* sH = (uint4*)Ah;
#pragma unroll 4
        for (int it = tid; it < 8 * D; it += 128) sH[it] = __ldg(gH + it);
    }

    // prefetch B tile 0 into buffer 0
    {
        const char* src = (const char*)(WhH + (size_t)jbase * D);
        for (int off = tid * 16; off < BBYTES; off += 2048) cp16(bb_b + off, src + off);
        CP_COMMIT();
    }

    float pacc[DNB][4];
#pragma unroll
    for (int q = 0; q < DNB; q++)
#pragma unroll
        for (int v = 0; v < 4; v++) pacc[q][v] = 0.f;

    const int arow = w * 16 + lrow;
    const int ra = w * 16 + row0;

    for (int tt = 0; tt < 16; tt++) {
        int j0 = jbase + tt * 64;
        __syncthreads();   // prop(tt-1) done reading B[(tt+1)&1] and adjS

        // adj[tt] tile prefetch: 64 rows x 64 cols f32, chunk-XOR swizzled
        {
            const char* asrc = (const char*)(adj + (size_t)i0 * NN + j0);
#pragma unroll
            for (int k = 0; k < 8; k++) {
                int idx = tid + k * 128;
                int row = idx >> 4, ch = idx & 15;
                cp16(adj_b + row * 256 + ((ch ^ (row & 7)) << 4),
                     asrc + (size_t)row * (NN * 4) + ch * 16);
            }
            CP_COMMIT();
        }
        if (tt + 1 < 16) {   // B[tt+1] prefetch
            const char* src = (const char*)(WhH + (size_t)(j0 + 64) * D);
            uint32_t dst = bb_b + ((tt + 1) & 1) * BBYTES;
            for (int off = tid * 16; off < BBYTES; off += 2048) cp16(dst + off, src + off);
            CP_COMMIT();
            asm volatile("cp.async.wait_group 2;" ::: "memory");  // B[tt] done
        } else {
            asm volatile("cp.async.wait_group 1;" ::: "memory");  // B[tt] done
        }
        __syncthreads();
        const uint32_t bcur = bb_b + (tt & 1) * BBYTES;

        // ---- score: S[16x64] per warp, single fp16 ----
        float sacc[8][4];
#pragma unroll
        for (int q = 0; q < 8; q++)
#pragma unroll
            for (int v = 0; v < 4; v++) sacc[q][v] = 0.f;

#pragma unroll
        for (int kc = 0; kc < KCH; kc++) {
            uint32_t achunk = (uint32_t)(((kc * 2 + lsel) ^ lx7) * 16);
            uint32_t ah[4];
            ldsm4(ah, ah_b + (uint32_t)arow * ROWB + achunk);
#pragma unroll
            for (int nh = 0; nh < 2; nh++) {
#pragma unroll
                for (int t = 0; t < 2; t++) {
                    int n00 = nh * 32 + t * 16;
                    uint32_t brow = (uint32_t)(n00 + lrow);
                    uint32_t boff = brow * ROWB + (uint32_t)(((kc * 2 + lsel) ^ (brow & 7)) * 16);
                    uint32_t bh[4];
                    ldsm4(bh, bcur + boff);
                    int nb = nh * 4 + t * 2;
                    mma_f16(sacc[nb],     ah, bh[0], bh[2]);
                    mma_f16(sacc[nb + 1], ah, bh[1], bh[3]);
                }
            }
        }

        // adj[tt] now needed
        if (tt + 1 < 16) {
            asm volatile("cp.async.wait_group 1;" ::: "memory");
        } else {
            asm volatile("cp.async.wait_group 0;" ::: "memory");
        }
        __syncthreads();

        // ---- weight epilogue: S -> w (fp16 A-fragments, in regs) ----
        uint32_t wh[4][4];
#pragma unroll
        for (int nb = 0; nb < 8; nb++) {
            int jp = j0 + nb * 8 + 2 * qp;
            int colc = nb * 8 + 2 * qp;
            int chunk = colc >> 2, within = colc & 3;
            int swo = ((chunk ^ (ra & 7)) << 2) + within;
            float2 a0 = *(const float2*)(adjS + ra * 64 + swo);
            float2 a8 = *(const float2*)(adjS + (ra + 8) * 64 + swo);
            float2 rj = __ldg((const float2*)(rvec + jp));   // inverse norms

            float ww[4];
            float sv[4] = {sacc[nb][0], sacc[nb][1], sacc[nb][2], sacc[nb][3]};
            float av[4] = {a0.x, a0.y, a8.x, a8.y};
            float rv[4] = {rj.x, rj.y, rj.x, rj.y};
            float riv[4] = {ri0, ri0, ri8, ri8};
            float div_[4] = {di0, di0, di8, di8};
            int giv[4] = {gi0, gi0, gi0 + 8, gi0 + 8};
            int gjv[4] = {jp, jp + 1, jp, jp + 1};
#pragma unroll
            for (int u = 0; u < 4; u++) {
                float a = av[u];
                float am = fmaxf(a, EPSV);
                float z = dc0 * (div_[u] * __frcp_rn(am) - 1.f) + dc1;
                float sp = softplusf(z);
                float e = sv[u] * riv[u] * rv[u];
                float att = e * a * sp;
                if (giv[u] == gjv[u]) att = 0.f;
                ww[u] = (att > 0.f ? c0 : c1) * att;
            }
            int kc = nb >> 1, o = (nb & 1) * 2;
            wh[kc][o] = pack_h(ww[0], ww[1]);
            wh[kc][o + 1] = pack_h(ww[2], ww[3]);
        }

        // ---- propagate: P += w @ Whj (B via ldmatrix.trans), single fp16 ----
#pragma unroll
        for (int kc = 0; kc < 4; kc++) {
            uint32_t jrow = (uint32_t)(kc * 16 + lrow);
#pragma unroll
            for (int dt = 0; dt < D / 16; dt++) {
                uint32_t boff = jrow * ROWB + (uint32_t)(((dt * 2 + lsel) ^ (jrow & 7)) * 16);
                uint32_t bh[4];
                ldsm4t(bh, bcur + boff);
                int p0 = dt * 2, p1 = dt * 2 + 1;
                mma_f16(pacc[p0], wh[kc], bh[0], bh[1]);
                mma_f16(pacc[p1], wh[kc], bh[2], bh[3]);
            }
        }
    }

    // ---- writeout ----
    float* dst0 = part + ((size_t)blockIdx.y * NN + gi0) * D;
    float* dst8 = dst0 + 8 * (size_t)D;
#pragma unroll
    for (int q = 0; q < DNB; q++) {
        int d = q * 8 + 2 * qp;
        *(float2*)(dst0 + d) = make_float2(pacc[q][0], pacc[q][1]);
        *(float2*)(dst8 + d) = make_float2(pacc[q][2], pacc[q][3]);
    }
}

// ---------------- epilogue layers 0..2 ----------------
__global__ void epi_kernel(const float* __restrict__ part, const float* __restrict__ Wh,
                           float* __restrict__ prev,
                           const float* __restrict__ cf, const float* __restrict__ sp,
                           float coeff) {
    int idx = blockIdx.x * 256 + threadIdx.x;
    float f0 = __ldg(cf), f1 = __ldg(cf + 1), f2 = __ldg(cf + 2);
    float mxc = fmaxf(f0, fmaxf(f1, f2));
    float e0 = __expf(f0 - mxc), e1 = __expf(f1 - mxc), e2 = __expf(f2 - mxc);
    float c2 = e2 / (e0 + e1 + e2);
    float s = softplusf(__ldg(sp));
    const size_t ST = (size_t)NN * 256;
    float psum = part[idx] + part[ST + idx] + part[2 * ST + idx] + part[3 * ST + idx];
    float inner = s * (psum + c2 * Wh[idx]);
    prev[idx] += coeff * eluf(inner);
}

// ---------------- final: log_softmax over 16 classes (part stride 64) --------
__global__ void final_kernel(const float* __restrict__ part, const float* __restrict__ Wh,
                             const float* __restrict__ cf, const float* __restrict__ sp,
                             float* __restrict__ out) {
    int row = blockIdx.x * blockDim.x + threadIdx.x;
    float f0 = __ldg(cf), f1 = __ldg(cf + 1), f2 = __ldg(cf + 2);
    float mxc = fmaxf(f0, fmaxf(f1, f2));
    float e0 = __expf(f0 - mxc), e1 = __expf(f1 - mxc), e2 = __expf(f2 - mxc);
    float c2 = e2 / (e0 + e1 + e2);
    float s = softplusf(__ldg(sp));
    const size_t ST = (size_t)NN * 64;

    float v[16];
    float mx = -3.4e38f;
#pragma unroll
    for (int c = 0; c < 16; c++) {
        size_t o = (size_t)row * 64 + c;
        float psum = part[o] + part[ST + o] + part[2 * ST + o] + part[3 * ST + o];
        float t = s * (psum + c2 * Wh[(size_t)row * 64 + c]);
        v[c] = t;
        mx = fmaxf(mx, t);
    }
    float lse = 0.f;
#pragma unroll
    for (int c = 0; c < 16; c++) lse += expf(v[c] - mx);
    lse = logf(lse);
#pragma unroll
    for (int c = 0; c < 16; c++) out[row * 16 + c] = v[c] - mx - lse;
}

// ---------------- host launcher ----------------
extern "C" void kernel_launch(void* const* d_in, const int* in_sizes, int n_in,
                              void* d_out, int out_size) {
    const float* x   = (const float*)d_in[0];
    const float* adj = (const float*)d_in[1];
    const float* Wf  = (const float*)d_in[2];
    const float* bf  = (const float*)d_in[3];
    const float* W0  = (const float*)d_in[4];
    const float* b0  = (const float*)d_in[5];
    const float* W1  = (const float*)d_in[6];
    const float* b1  = (const float*)d_in[7];
    const float* W2  = (const float*)d_in[8];
    const float* b2  = (const float*)d_in[9];
    const float* W3  = (const float*)d_in[10];
    const float* b3  = (const float*)d_in[11];
    const float* dcs = (const float*)d_in[12];
    const float* cfs = (const float*)d_in[13];
    const float* sps = (const float*)d_in[14];
    float* out = (float*)d_out;

    float *p_prev, *p_Wh, *p_part, *p_diag, *p_r;
    __half *p_WhH;
    cudaGetSymbolAddress((void**)&p_prev, g_prev);
    cudaGetSymbolAddress((void**)&p_Wh, g_Wh);
    cudaGetSymbolAddress((void**)&p_part, g_part);
    cudaGetSymbolAddress((void**)&p_diag, g_diag);
    cudaGetSymbolAddress((void**)&p_r, g_rinv);
    cudaGetSymbolAddress((void**)&p_WhH, g_WhH);

    // smem: A(64xD) + 2xB(64xD) + adj 16KB swizzled
    const int SM256 = 64 * 512 + 2 * 32768 + 16384;  // 114688 -> 2 CTAs/SM
    const int SM64  = 64 * 128 + 2 * 8192 + 16384;   //  40960
    cudaFuncSetAttribute(fused_mma<256>, cudaFuncAttributeMaxDynamicSharedMemorySize, SM256);
    cudaFuncSetAttribute(fused_mma<64>,  cudaFuncAttributeMaxDynamicSharedMemorySize, SM64);

    const float cI1 = 1.0f;
    const float cI2 = logf(1.0f / 27.0f + 1.0f);
    const float cI3 = logf(1.0f / 64.0f + 1.0f);

    diag_kernel<<<NN / 256, 256>>>(adj, p_diag);
    gemm_bias_kernel<<<dim3(64, 4), 256>>>(x, Wf, bf, p_prev, 512, 1);

    // ---- layer 0 ----
    gemm_bias_kernel<<<dim3(64, 4), 256>>>(x, W0, b0, p_Wh, 512, 0);
    rownorm_kernel<<<512, 256>>>(p_Wh, p_r, 256);
    cvt_kernel<256><<<512, 256>>>(p_Wh, p_WhH);
    fused_mma<256><<<dim3(64, 4), 128, SM256>>>(p_WhH, p_r, p_diag, adj,
                                                dcs + 0, cfs + 0, p_part);
    epi_kernel<<<NN, 256>>>(p_part, p_Wh, p_prev, cfs + 0, sps + 0, cI1);

    // ---- layer 1 ----
    gemm_bias_kernel<<<dim3(64, 4), 256>>>(p_prev, W1, b1, p_Wh, 256, 0);
    rownorm_kernel<<<512, 256>>>(p_Wh, p_r, 256);
    cvt_kernel<256><<<512, 256>>>(p_Wh, p_WhH);
    fused_mma<256><<<dim3(64, 4), 128, SM256>>>(p_WhH, p_r, p_diag, adj,
                                                dcs + 2, cfs + 3, p_part);
    epi_kernel<<<NN, 256>>>(p_part, p_Wh, p_prev, cfs + 3, sps + 1, cI2);

    // ---- layer 2 ----
    gemm_bias_kernel<<<dim3(64, 4), 256>>>(p_prev, W2, b2, p_Wh, 256, 0);
    rownorm_kernel<<<512, 256>>>(p_Wh, p_r, 256);
    cvt_kernel<256><<<512, 256>>>(p_Wh, p_WhH);
    fused_mma<256><<<dim3(64, 4), 128, SM256>>>(p_WhH, p_r, p_diag, adj,
                                                dcs + 4, cfs + 6, p_part);
    epi_kernel<<<NN, 256>>>(p_part, p_Wh, p_prev, cfs + 6, sps + 2, cI3);

    // ---- layer 3 (D=16 zero-padded to 64) ----
    wh16_kernel<<<NN * 64 / 256, 256>>>(p_prev, W3, b3, p_Wh);
    rownorm_kernel<<<512, 256>>>(p_Wh, p_r, 64);
    cvt_kernel<64><<<128, 256>>>(p_Wh, p_WhH);
    fused_mma<64><<<dim3(64, 4), 128, SM64>>>(p_WhH, p_r, p_diag, adj,
                                              dcs + 6, cfs + 9, p_part);
    final_kernel<<<NN / 256, 256>>>(p_part, p_Wh, cfs + 9, sps + 3, out);
}

// round 9
// speedup vs baseline: 4.4181x; 1.0003x over previous
#include <cuda_runtime.h>
#include <cuda_fp16.h>
#include <math.h>
#include <stdint.h>

#define NN 4096
#define EPSV 1e-9f

// ---------------- device scratch (static, allocation-free) ----------------
__device__ float g_prev[NN * 256];
__device__ float g_Wh[NN * 256];
__device__ float g_part[4 * NN * 256];   // 4-way j-split partial propagate sums
__device__ float g_diag[NN];
__device__ float g_rinv[NN];             // 1 / ||Wh_i||
__device__ __half g_WhH[NN * 256];       // Wh fp16, swizzled chunks

// ---------------- asm helpers ----------------
__device__ __forceinline__ uint32_t smem_u32(const void* p) {
    return (uint32_t)__cvta_generic_to_shared((void*)p);
}
__device__ __forceinline__ void ldsm4(uint32_t* r, uint32_t addr) {
    asm volatile("ldmatrix.sync.aligned.m8n8.x4.shared.b16 {%0,%1,%2,%3}, [%4];"
                 : "=r"(r[0]), "=r"(r[1]), "=r"(r[2]), "=r"(r[3]) : "r"(addr));
}
__device__ __forceinline__ void ldsm4t(uint32_t* r, uint32_t addr) {
    asm volatile("ldmatrix.sync.aligned.m8n8.x4.trans.shared.b16 {%0,%1,%2,%3}, [%4];"
                 : "=r"(r[0]), "=r"(r[1]), "=r"(r[2]), "=r"(r[3]) : "r"(addr));
}
__device__ __forceinline__ void mma_f16(float* c, const uint32_t* a, uint32_t b0, uint32_t b1) {
    asm volatile("mma.sync.aligned.m16n8k16.row.col.f32.f16.f16.f32 "
                 "{%0,%1,%2,%3}, {%4,%5,%6,%7}, {%8,%9}, {%0,%1,%2,%3};"
                 : "+f"(c[0]), "+f"(c[1]), "+f"(c[2]), "+f"(c[3])
                 : "r"(a[0]), "r"(a[1]), "r"(a[2]), "r"(a[3]), "r"(b0), "r"(b1));
}
__device__ __forceinline__ void cp16(uint32_t dst, const void* src) {
    asm volatile("cp.async.cg.shared.global [%0], [%1], 16;" :: "r"(dst), "l"(src));
}
#define CP_COMMIT() asm volatile("cp.async.commit_group;" ::: "memory")

// ---------------- math helpers ----------------
__device__ __forceinline__ float softplusf(float z) {
    return (z > 15.f) ? z : __logf(1.f + __expf(z));
}
__device__ __forceinline__ float eluf(float x) { return x > 0.f ? x : expm1f(x); }

__device__ __forceinline__ void fma16(float (&p)[4][4], float4 a, float4 b) {
    p[0][0] += a.x * b.x; p[0][1] += a.x * b.y; p[0][2] += a.x * b.z; p[0][3] += a.x * b.w;
    p[1][0] += a.y * b.x; p[1][1] += a.y * b.y; p[1][2] += a.y * b.z; p[1][3] += a.y * b.w;
    p[2][0] += a.z * b.x; p[2][1] += a.z * b.y; p[2][2] += a.z * b.z; p[2][3] += a.z * b.w;
    p[3][0] += a.w * b.x; p[3][1] += a.w * b.y; p[3][2] += a.w * b.z; p[3][3] += a.w * b.w;
}

__device__ __forceinline__ uint32_t pack_h(float a, float b) {
    __half2 h = __floats2half2_rn(a, b);
    return *(uint32_t*)&h;
}

// ---------------- Wh fp32 -> swizzled fp16 global array ----------------
// chunk layout: elem16 offset = row*D + (c ^ (row&7))*8 + (k&7), c = k>>3.
template <int D>
__global__ void cvt_kernel(const float* __restrict__ src, __half* __restrict__ H) {
    int idx = blockIdx.x * 256 + threadIdx.x;   // NN*D/8 chunks
    int row = idx / (D / 8);
    int c = idx % (D / 8);
    const float* s = src + (size_t)row * D + c * 8;
    float4 v0 = __ldg((const float4*)s);
    float4 v1 = __ldg((const float4*)(s + 4));
    int dcn = c ^ (row & 7);
    size_t off = (size_t)row * D + dcn * 8;
    __half2 h0 = __floats2half2_rn(v0.x, v0.y), h1 = __floats2half2_rn(v0.z, v0.w);
    __half2 h2 = __floats2half2_rn(v1.x, v1.y), h3 = __floats2half2_rn(v1.z, v1.w);
    *(uint4*)(H + off) = make_uint4(*(uint32_t*)&h0, *(uint32_t*)&h1,
                                    *(uint32_t*)&h2, *(uint32_t*)&h3);
}

// ---------------- small kernels ----------------
__global__ void diag_kernel(const float* __restrict__ adj, float* __restrict__ dg) {
    int i = blockIdx.x * 256 + threadIdx.x;
    dg[i] = adj[(size_t)i * (NN + 1)];
}

__global__ __launch_bounds__(256)
void gemm_bias_kernel(const float* __restrict__ A, const float* __restrict__ W,
                      const float* __restrict__ bias, float* __restrict__ C,
                      int K, int do_elu) {
    __shared__ float sA[16][68];
    __shared__ float sB[16][68];
    const int tid = threadIdx.x;
    const int ty = tid >> 4, tx = tid & 15;
    const int i0 = blockIdx.x * 64, j0 = blockIdx.y * 64;
    const int mload = tid >> 4;
    const int kload = tid & 15;
    const int kload2 = tid >> 6;
    const int nload = tid & 63;

    float p[4][4];
#pragma unroll
    for (int u = 0; u < 4; u++)
#pragma unroll
        for (int v = 0; v < 4; v++) p[u][v] = 0.f;

    for (int kb = 0; kb < K; kb += 16) {
        __syncthreads();
#pragma unroll
        for (int r = 0; r < 4; r++)
            sA[kload][mload + 16 * r] = A[(size_t)(i0 + mload + 16 * r) * K + kb + kload];
#pragma unroll
        for (int r = 0; r < 4; r++)
            sB[kload2 + 4 * r][nload] = W[(size_t)(kb + kload2 + 4 * r) * 256 + j0 + nload];
        __syncthreads();
#pragma unroll
        for (int kk = 0; kk < 16; kk++) {
            float4 a = *(const float4*)&sA[kk][4 * ty];
            float4 b = *(const float4*)&sB[kk][4 * tx];
            fma16(p, a, b);
        }
    }
#pragma unroll
    for (int u = 0; u < 4; u++) {
#pragma unroll
        for (int v = 0; v < 4; v++) {
            float val = p[u][v] + __ldg(bias + j0 + 4 * tx + v);
            if (do_elu) val = eluf(val);
            C[(size_t)(i0 + 4 * ty + u) * 256 + j0 + 4 * tx + v] = val;
        }
    }
}

// layer 3: Wh64 = zero-pad(prev @ W3 + b3) to [N,64]
__global__ void wh16_kernel(const float* __restrict__ H, const float* __restrict__ W3,
                            const float* __restrict__ b3, float* __restrict__ Wh) {
    int idx = blockIdx.x * 256 + threadIdx.x;  // NN*64
    int i = idx >> 6, c = idx & 63;
    float s = 0.f;
    if (c < 16) {
        s = __ldg(b3 + c);
        const float* h = H + (size_t)i * 256;
#pragma unroll 8
        for (int k = 0; k < 256; k++) s += h[k] * __ldg(W3 + k * 16 + c);
    }
    Wh[idx] = s;
}

// outputs INVERSE row norm
__global__ void rownorm_kernel(const float* __restrict__ Wh, float* __restrict__ r, int D) {
    int row = blockIdx.x * 8 + (threadIdx.x >> 5);
    int lane = threadIdx.x & 31;
    float s = 0.f;
    for (int k = lane; k < D; k += 32) {
        float v = Wh[(size_t)row * D + k];
        s += v * v;
    }
#pragma unroll
    for (int o = 16; o; o >>= 1) s += __shfl_xor_sync(0xffffffffu, s, o);
    if (lane == 0) r[row] = 1.f / fmaxf(sqrtf(s), 1e-5f);
}

// ---------------- fused mma.sync attention layer (single fp16, BM=64) --------
// grid (64, 4): 64-row i tiles x 4-way j split; 128 threads, 4 warps over i.
// SMEM: Ah[64xD] fp16 + B double buffer (2 x 64xD fp16) + adj tile [64][64] f32
// (chunk-XOR swizzled). Sized for 2 CTAs/SM.
template <int D>  // 256, or 64 (layer 3 zero-padded)
__global__ __launch_bounds__(128)
void fused_mma(const __half* __restrict__ WhH,
               const float* __restrict__ rvec,
               const float* __restrict__ diagv, const float* __restrict__ adj,
               const float* __restrict__ dc, const float* __restrict__ cf,
               float* __restrict__ part) {
    constexpr int KCH = D / 16;   // score k-chunks
    constexpr int DNB = D / 8;    // propagate n-blocks (P accumulators)
    constexpr int ROWB = 2 * D;   // smem row bytes (fp16)
    constexpr int BBYTES = 64 * ROWB;

    extern __shared__ char sm[];
    char* Ah = sm;
    char* Bb = sm + 64 * ROWB;
    float* adjS = (float*)(sm + 64 * ROWB + 2 * BBYTES);
    const uint32_t ah_b = smem_u32(Ah);
    const uint32_t bb_b = smem_u32(Bb);
    const uint32_t adj_b = smem_u32(adjS);

    const int tid = threadIdx.x;
    const int w = tid >> 5, lane = tid & 31;  // 4 warps
    const int i0 = blockIdx.x * 64;
    const int jbase = blockIdx.y * (NN / 4);
    const int row0 = lane >> 2;
    const int qp = lane & 3;
    const int gi0 = i0 + w * 16 + row0;

    const int lrow = lane & 15;
    const int lsel = lane >> 4;
    const int lx7 = lane & 7;

    // per-layer scalars
    float dc0 = __ldg(dc), dc1 = __ldg(dc + 1);
    float f0 = __ldg(cf), f1 = __ldg(cf + 1), f2 = __ldg(cf + 2);
    float mxc = fmaxf(f0, fmaxf(f1, f2));
    float e0 = __expf(f0 - mxc), e1 = __expf(f1 - mxc), e2 = __expf(f2 - mxc);
    float inv = 1.f / (e0 + e1 + e2);
    float c0 = e0 * inv, c1 = e1 * inv;
    float ri0 = __ldg(rvec + gi0), ri8 = __ldg(rvec + gi0 + 8);   // inverse norms
    float di0 = __ldg(diagv + gi0), di8 = __ldg(diagv + gi0 + 8);

    // A tile: raw copy (swizzle preserved: i0 multiple of 64 keeps row mod 8)
    {
        const uint4* gH = (const uint4*)(WhH + (size_t)i0 * D);
        uint4* sH = (uint4*)Ah;
#pragma unroll 4
        for (int it = tid; it < 8 * D; it += 128) sH[it] = __ldg(gH + it);
    }

    // prefetch B tile 0 into buffer 0
    {
        const char* src = (const char*)(WhH + (size_t)jbase * D);
        for (int off = tid * 16; off < BBYTES; off += 2048) cp16(bb_b + off, src + off);
        CP_COMMIT();
    }

    float pacc[DNB][4];
#pragma unroll
    for (int q = 0; q < DNB; q++)
#pragma unroll
        for (int v = 0; v < 4; v++) pacc[q][v] = 0.f;

    const int arow = w * 16 + lrow;
    const int ra = w * 16 + row0;

    for (int tt = 0; tt < 16; tt++) {
        int j0 = jbase + tt * 64;
        __syncthreads();   // prop(tt-1) done reading B[(tt+1)&1] and adjS

        // adj[tt] tile prefetch: 64 rows x 64 cols f32, chunk-XOR swizzled
        {
            const char* asrc = (const char*)(adj + (size_t)i0 * NN + j0);
#pragma unroll
            for (int k = 0; k < 8; k++) {
                int idx = tid + k * 128;
                int row = idx >> 4, ch = idx & 15;
                cp16(adj_b + row * 256 + ((ch ^ (row & 7)) << 4),
                     asrc + (size_t)row * (NN * 4) + ch * 16);
            }
            CP_COMMIT();
        }
        if (tt + 1 < 16) {   // B[tt+1] prefetch
            const char* src = (const char*)(WhH + (size_t)(j0 + 64) * D);
            uint32_t dst = bb_b + ((tt + 1) & 1) * BBYTES;
            for (int off = tid * 16; off < BBYTES; off += 2048) cp16(dst + off, src + off);
            CP_COMMIT();
            asm volatile("cp.async.wait_group 2;" ::: "memory");  // B[tt] done
        } else {
            asm volatile("cp.async.wait_group 1;" ::: "memory");  // B[tt] done
        }
        __syncthreads();
        const uint32_t bcur = bb_b + (tt & 1) * BBYTES;

        // ---- score: S[16x64] per warp, single fp16 ----
        float sacc[8][4];
#pragma unroll
        for (int q = 0; q < 8; q++)
#pragma unroll
            for (int v = 0; v < 4; v++) sacc[q][v] = 0.f;

#pragma unroll
        for (int kc = 0; kc < KCH; kc++) {
            uint32_t achunk = (uint32_t)(((kc * 2 + lsel) ^ lx7) * 16);
            uint32_t ah[4];
            ldsm4(ah, ah_b + (uint32_t)arow * ROWB + achunk);
#pragma unroll
            for (int nh = 0; nh < 2; nh++) {
#pragma unroll
                for (int t = 0; t < 2; t++) {
                    int n00 = nh * 32 + t * 16;
                    uint32_t brow = (uint32_t)(n00 + lrow);
                    uint32_t boff = brow * ROWB + (uint32_t)(((kc * 2 + lsel) ^ (brow & 7)) * 16);
                    uint32_t bh[4];
                    ldsm4(bh, bcur + boff);
                    int nb = nh * 4 + t * 2;
                    mma_f16(sacc[nb],     ah, bh[0], bh[2]);
                    mma_f16(sacc[nb + 1], ah, bh[1], bh[3]);
                }
            }
        }

        // adj[tt] now needed
        if (tt + 1 < 16) {
            asm volatile("cp.async.wait_group 1;" ::: "memory");
        } else {
            asm volatile("cp.async.wait_group 0;" ::: "memory");
        }
        __syncthreads();

        // ---- weight epilogue: S -> w (fp16 A-fragments, in regs) ----
        uint32_t wh[4][4];
#pragma unroll
        for (int nb = 0; nb < 8; nb++) {
            int jp = j0 + nb * 8 + 2 * qp;
            int colc = nb * 8 + 2 * qp;
            int chunk = colc >> 2, within = colc & 3;
            int swo = ((chunk ^ (ra & 7)) << 2) + within;
            float2 a0 = *(const float2*)(adjS + ra * 64 + swo);
            float2 a8 = *(const float2*)(adjS + (ra + 8) * 64 + swo);
            float2 rj = __ldg((const float2*)(rvec + jp));   // inverse norms

            float ww[4];
            float sv[4] = {sacc[nb][0], sacc[nb][1], sacc[nb][2], sacc[nb][3]};
            float av[4] = {a0.x, a0.y, a8.x, a8.y};
            float rv[4] = {rj.x, rj.y, rj.x, rj.y};
            float riv[4] = {ri0, ri0, ri8, ri8};
            float div_[4] = {di0, di0, di8, di8};
            int giv[4] = {gi0, gi0, gi0 + 8, gi0 + 8};
            int gjv[4] = {jp, jp + 1, jp, jp + 1};
#pragma unroll
            for (int u = 0; u < 4; u++) {
                float a = av[u];
                float am = fmaxf(a, EPSV);
                float z = dc0 * (div_[u] * __frcp_rn(am) - 1.f) + dc1;
                float sp = softplusf(z);
                float e = sv[u] * riv[u] * rv[u];
                float att = e * a * sp;
                if (giv[u] == gjv[u]) att = 0.f;
                ww[u] = (att > 0.f ? c0 : c1) * att;
            }
            int kc = nb >> 1, o = (nb & 1) * 2;
            wh[kc][o] = pack_h(ww[0], ww[1]);
            wh[kc][o + 1] = pack_h(ww[2], ww[3]);
        }

        // ---- propagate: P += w @ Whj (B via ldmatrix.trans), single fp16 ----
#pragma unroll
        for (int kc = 0; kc < 4; kc++) {
            uint32_t jrow = (uint32_t)(kc * 16 + lrow);
#pragma unroll
            for (int dt = 0; dt < D / 16; dt++) {
                uint32_t boff = jrow * ROWB + (uint32_t)(((dt * 2 + lsel) ^ (jrow & 7)) * 16);
                uint32_t bh[4];
                ldsm4t(bh, bcur + boff);
                int p0 = dt * 2, p1 = dt * 2 + 1;
                mma_f16(pacc[p0], wh[kc], bh[0], bh[1]);
                mma_f16(pacc[p1], wh[kc], bh[2], bh[3]);
            }
        }
    }

    // ---- writeout ----
    float* dst0 = part + ((size_t)blockIdx.y * NN + gi0) * D;
    float* dst8 = dst0 + 8 * (size_t)D;
#pragma unroll
    for (int q = 0; q < DNB; q++) {
        int d = q * 8 + 2 * qp;
        *(float2*)(dst0 + d) = make_float2(pacc[q][0], pacc[q][1]);
        *(float2*)(dst8 + d) = make_float2(pacc[q][2], pacc[q][3]);
    }
}

// ---------------- epilogue layers 0..2 ----------------
__global__ void epi_kernel(const float* __restrict__ part, const float* __restrict__ Wh,
                           float* __restrict__ prev,
                           const float* __restrict__ cf, const float* __restrict__ sp,
                           float coeff) {
    int idx = blockIdx.x * 256 + threadIdx.x;
    float f0 = __ldg(cf), f1 = __ldg(cf + 1), f2 = __ldg(cf + 2);
    float mxc = fmaxf(f0, fmaxf(f1, f2));
    float e0 = __expf(f0 - mxc), e1 = __expf(f1 - mxc), e2 = __expf(f2 - mxc);
    float c2 = e2 / (e0 + e1 + e2);
    float s = softplusf(__ldg(sp));
    const size_t ST = (size_t)NN * 256;
    float psum = part[idx] + part[ST + idx] + part[2 * ST + idx] + part[3 * ST + idx];
    float inner = s * (psum + c2 * Wh[idx]);
    prev[idx] += coeff * eluf(inner);
}

// ---------------- final: log_softmax over 16 classes (part stride 64) --------
__global__ void final_kernel(const float* __restrict__ part, const float* __restrict__ Wh,
                             const float* __restrict__ cf, const float* __restrict__ sp,
                             float* __restrict__ out) {
    int row = blockIdx.x * blockDim.x + threadIdx.x;
    float f0 = __ldg(cf), f1 = __ldg(cf + 1), f2 = __ldg(cf + 2);
    float mxc = fmaxf(f0, fmaxf(f1, f2));
    float e0 = __expf(f0 - mxc), e1 = __expf(f1 - mxc), e2 = __expf(f2 - mxc);
    float c2 = e2 / (e0 + e1 + e2);
    float s = softplusf(__ldg(sp));
    const size_t ST = (size_t)NN * 64;

    float v[16];
    float mx = -3.4e38f;
#pragma unroll
    for (int c = 0; c < 16; c++) {
        size_t o = (size_t)row * 64 + c;
        float psum = part[o] + part[ST + o] + part[2 * ST + o] + part[3 * ST + o];
        float t = s * (psum + c2 * Wh[(size_t)row * 64 + c]);
        v[c] = t;
        mx = fmaxf(mx, t);
    }
    float lse = 0.f;
#pragma unroll
    for (int c = 0; c < 16; c++) lse += expf(v[c] - mx);
    lse = logf(lse);
#pragma unroll
    for (int c = 0; c < 16; c++) out[row * 16 + c] = v[c] - mx - lse;
}

// ---------------- host launcher ----------------
extern "C" void kernel_launch(void* const* d_in, const int* in_sizes, int n_in,
                              void* d_out, int out_size) {
    const float* x   = (const float*)d_in[0];
    const float* adj = (const float*)d_in[1];
    const float* Wf  = (const float*)d_in[2];
    const float* bf  = (const float*)d_in[3];
    const float* W0  = (const float*)d_in[4];
    const float* b0  = (const float*)d_in[5];
    const float* W1  = (const float*)d_in[6];
    const float* b1  = (const float*)d_in[7];
    const float* W2  = (const float*)d_in[8];
    const float* b2  = (const float*)d_in[9];
    const float* W3  = (const float*)d_in[10];
    const float* b3  = (const float*)d_in[11];
    const float* dcs = (const float*)d_in[12];
    const float* cfs = (const float*)d_in[13];
    const float* sps = (const float*)d_in[14];
    float* out = (float*)d_out;

    float *p_prev, *p_Wh, *p_part, *p_diag, *p_r;
    __half *p_WhH;
    cudaGetSymbolAddress((void**)&p_prev, g_prev);
    cudaGetSymbolAddress((void**)&p_Wh, g_Wh);
    cudaGetSymbolAddress((void**)&p_part, g_part);
    cudaGetSymbolAddress((void**)&p_diag, g_diag);
    cudaGetSymbolAddress((void**)&p_r, g_rinv);
    cudaGetSymbolAddress((void**)&p_WhH, g_WhH);

    // smem: A(64xD) + 2xB(64xD) + adj 16KB swizzled
    const int SM256 = 64 * 512 + 2 * 32768 + 16384;  // 114688 -> 2 CTAs/SM
    const int SM64  = 64 * 128 + 2 * 8192 + 16384;   //  40960
    cudaFuncSetAttribute(fused_mma<256>, cudaFuncAttributeMaxDynamicSharedMemorySize, SM256);
    cudaFuncSetAttribute(fused_mma<64>,  cudaFuncAttributeMaxDynamicSharedMemorySize, SM64);

    const float cI1 = 1.0f;
    const float cI2 = logf(1.0f / 27.0f + 1.0f);
    const float cI3 = logf(1.0f / 64.0f + 1.0f);

    diag_kernel<<<NN / 256, 256>>>(adj, p_diag);
    gemm_bias_kernel<<<dim3(64, 4), 256>>>(x, Wf, bf, p_prev, 512, 1);

    // ---- layer 0 ----
    gemm_bias_kernel<<<dim3(64, 4), 256>>>(x, W0, b0, p_Wh, 512, 0);
    rownorm_kernel<<<512, 256>>>(p_Wh, p_r, 256);
    cvt_kernel<256><<<512, 256>>>(p_Wh, p_WhH);
    fused_mma<256><<<dim3(64, 4), 128, SM256>>>(p_WhH, p_r, p_diag, adj,
                                                dcs + 0, cfs + 0, p_part);
    epi_kernel<<<NN, 256>>>(p_part, p_Wh, p_prev, cfs + 0, sps + 0, cI1);

    // ---- layer 1 ----
    gemm_bias_kernel<<<dim3(64, 4), 256>>>(p_prev, W1, b1, p_Wh, 256, 0);
    rownorm_kernel<<<512, 256>>>(p_Wh, p_r, 256);
    cvt_kernel<256><<<512, 256>>>(p_Wh, p_WhH);
    fused_mma<256><<<dim3(64, 4), 128, SM256>>>(p_WhH, p_r, p_diag, adj,
                                                dcs + 2, cfs + 3, p_part);
    epi_kernel<<<NN, 256>>>(p_part, p_Wh, p_prev, cfs + 3, sps + 1, cI2);

    // ---- layer 2 ----
    gemm_bias_kernel<<<dim3(64, 4), 256>>>(p_prev, W2, b2, p_Wh, 256, 0);
    rownorm_kernel<<<512, 256>>>(p_Wh, p_r, 256);
    cvt_kernel<256><<<512, 256>>>(p_Wh, p_WhH);
    fused_mma<256><<<dim3(64, 4), 128, SM256>>>(p_WhH, p_r, p_diag, adj,
                                                dcs + 4, cfs + 6, p_part);
    epi_kernel<<<NN, 256>>>(p_part, p_Wh, p_prev, cfs + 6, sps + 2, cI3);

    // ---- layer 3 (D=16 zero-padded to 64) ----
    wh16_kernel<<<NN * 64 / 256, 256>>>(p_prev, W3, b3, p_Wh);
    rownorm_kernel<<<512, 256>>>(p_Wh, p_r, 64);
    cvt_kernel<64><<<128, 256>>>(p_Wh, p_WhH);
    fused_mma<64><<<dim3(64, 4), 128, SM64>>>(p_WhH, p_r, p_diag, adj,
                                              dcs + 6, cfs + 9, p_part);
    final_kernel<<<NN / 256, 256>>>(p_part, p_Wh, cfs + 9, sps + 3, out);
}